// round 1
// baseline (speedup 1.0000x reference)
#include <cuda_runtime.h>

// Problem constants
#define B_  2
#define S_  2048
#define D_  1024
#define H_  16
#define HD_ 64
#define M_  (B_*S_)   // 4096 rows

// Scratch (device globals: no allocation allowed in kernel_launch)
__device__ float g_q[M_*D_];
__device__ float g_k[M_*D_];
__device__ float g_v[M_*D_];
__device__ float g_c[M_*D_];

// ---------------------------------------------------------------------------
// GEMM: Y[m,n] = sum_k X[m,k] * Wt[n,k]  (+ bias[n])   (torch Linear x @ W.T)
// M=4096, N=1024, K=1024. Tiles: BM=128, BN=64, BK=16. 256 threads, 8x4 micro.
// ---------------------------------------------------------------------------
__global__ __launch_bounds__(256) void gemm_xwT(
    const float* __restrict__ X, const float* __restrict__ Wt,
    const float* __restrict__ bias, float* __restrict__ Y)
{
    const int K = D_, N = D_;
    __shared__ float Xs[16][128];
    __shared__ float Ws[16][64];

    int t  = threadIdx.x;
    int n0 = blockIdx.x * 64;
    int m0 = blockIdx.y * 128;
    int tx = t & 15, ty = t >> 4;

    // load mapping
    int xr = t >> 1, xc = (t & 1) * 8;   // X: 128 rows x 16 k
    int wr = t >> 2, wc = (t & 3) * 4;   // W: 64 rows x 16 k
    const float* Xp = X  + (size_t)(m0 + xr) * K + xc;
    const float* Wp = Wt + (size_t)(n0 + wr) * K + wc;

    float acc[8][4];
    #pragma unroll
    for (int i = 0; i < 8; i++)
        #pragma unroll
        for (int j = 0; j < 4; j++) acc[i][j] = 0.f;

    // prefetch first tile
    float4 xv0 = *(const float4*)(Xp);
    float4 xv1 = *(const float4*)(Xp + 4);
    float4 wv  = *(const float4*)(Wp);

    for (int k0 = 0; k0 < K; k0 += 16) {
        __syncthreads();
        Xs[xc+0][xr] = xv0.x; Xs[xc+1][xr] = xv0.y; Xs[xc+2][xr] = xv0.z; Xs[xc+3][xr] = xv0.w;
        Xs[xc+4][xr] = xv1.x; Xs[xc+5][xr] = xv1.y; Xs[xc+6][xr] = xv1.z; Xs[xc+7][xr] = xv1.w;
        Ws[wc+0][wr] = wv.x;  Ws[wc+1][wr] = wv.y;  Ws[wc+2][wr] = wv.z;  Ws[wc+3][wr] = wv.w;
        __syncthreads();

        if (k0 + 16 < K) {  // prefetch next tile under compute
            xv0 = *(const float4*)(Xp + k0 + 16);
            xv1 = *(const float4*)(Xp + k0 + 20);
            wv  = *(const float4*)(Wp + k0 + 16);
        }

        #pragma unroll
        for (int kk = 0; kk < 16; kk++) {
            float4 a0 = *(const float4*)&Xs[kk][ty*8];
            float4 a1 = *(const float4*)&Xs[kk][ty*8+4];
            float4 b  = *(const float4*)&Ws[kk][tx*4];
            float av[8] = {a0.x, a0.y, a0.z, a0.w, a1.x, a1.y, a1.z, a1.w};
            float bv[4] = {b.x, b.y, b.z, b.w};
            #pragma unroll
            for (int i = 0; i < 8; i++)
                #pragma unroll
                for (int j = 0; j < 4; j++)
                    acc[i][j] = fmaf(av[i], bv[j], acc[i][j]);
        }
    }

    float4 bvec = make_float4(0.f, 0.f, 0.f, 0.f);
    if (bias) bvec = *(const float4*)(bias + n0 + tx*4);

    #pragma unroll
    for (int i = 0; i < 8; i++) {
        float4 o;
        o.x = acc[i][0] + bvec.x;
        o.y = acc[i][1] + bvec.y;
        o.z = acc[i][2] + bvec.z;
        o.w = acc[i][3] + bvec.w;
        *(float4*)(Y + (size_t)(m0 + ty*8 + i) * N + n0 + tx*4) = o;
    }
}

// ---------------------------------------------------------------------------
// Flash attention (causal). 1 thread = 1 query row. BM=128 rows/block,
// K/V staged in 64-key smem tiles, online softmax over 16-key chunks.
// Q row + 64-float accumulator live entirely in registers.
// Layouts: Q/K/V/CTX as [b, s, D] with head h occupying cols [h*64, h*64+64).
// ---------------------------------------------------------------------------
#define KSTR 68   // smem row stride in floats (pad 64 -> 68, keeps 16B align)

__global__ __launch_bounds__(128) void attn_kernel(
    const float* __restrict__ Q, const float* __restrict__ Kg,
    const float* __restrict__ Vg, float* __restrict__ O)
{
    __shared__ float Ks[64 * KSTR];
    __shared__ float Vs[64 * KSTR];

    int tid = threadIdx.x;
    int qt  = (int)(gridDim.x - 1u - blockIdx.x);   // heavy q-tiles launch first
    int h   = blockIdx.y, b = blockIdx.z;
    int row = qt * 128 + tid;

    const float4* qp = (const float4*)(Q + ((size_t)(b*S_ + row))*D_ + h*HD_);
    float4 q4[16];
    #pragma unroll
    for (int i = 0; i < 16; i++) {
        float4 v = qp[i];
        q4[i] = make_float4(v.x*0.125f, v.y*0.125f, v.z*0.125f, v.w*0.125f); // 1/sqrt(64)
    }

    float4 acc[16];
    #pragma unroll
    for (int i = 0; i < 16; i++) acc[i] = make_float4(0.f, 0.f, 0.f, 0.f);
    float m = -1e30f, l = 0.f;

    int kr = tid >> 1;            // smem row this thread loads
    int hf = (tid & 1) * 8;       // which 8 float4s of the row

    int ntiles = 2*qt + 2;
    for (int kt = 0; kt < ntiles; kt++) {
        __syncthreads();
        {
            const float4* kp = (const float4*)(Kg + ((size_t)(b*S_ + kt*64 + kr))*D_ + h*HD_);
            const float4* vp = (const float4*)(Vg + ((size_t)(b*S_ + kt*64 + kr))*D_ + h*HD_);
            float4* ksr = (float4*)(Ks + kr*KSTR);
            float4* vsr = (float4*)(Vs + kr*KSTR);
            #pragma unroll
            for (int i = 0; i < 8; i++) ksr[hf + i] = kp[hf + i];
            #pragma unroll
            for (int i = 0; i < 8; i++) vsr[hf + i] = vp[hf + i];
        }
        __syncthreads();

        bool masked = (kt >= 2*qt);   // tiles 0..2qt-1 are fully below diagonal
        int kb0 = kt * 64;

        #pragma unroll 1
        for (int c = 0; c < 4; c++) {
            float s[16];
            #pragma unroll
            for (int j = 0; j < 16; j++) {
                const float4* kj = (const float4*)(Ks + (c*16 + j)*KSTR);
                float sj = 0.f;
                #pragma unroll
                for (int d = 0; d < 16; d++) {
                    float4 kv = kj[d];   // warp-broadcast LDS
                    sj = fmaf(q4[d].x, kv.x, sj);
                    sj = fmaf(q4[d].y, kv.y, sj);
                    sj = fmaf(q4[d].z, kv.z, sj);
                    sj = fmaf(q4[d].w, kv.w, sj);
                }
                s[j] = sj;
            }
            if (masked) {
                #pragma unroll
                for (int j = 0; j < 16; j++)
                    if (kb0 + c*16 + j > row) s[j] = -1e30f;
            }
            float cm = s[0];
            #pragma unroll
            for (int j = 1; j < 16; j++) cm = fmaxf(cm, s[j]);
            float mn = fmaxf(m, cm);
            float r  = __expf(m - mn);
            l *= r;
            #pragma unroll
            for (int d = 0; d < 16; d++) {
                acc[d].x *= r; acc[d].y *= r; acc[d].z *= r; acc[d].w *= r;
            }
            #pragma unroll
            for (int j = 0; j < 16; j++) {
                float p = __expf(s[j] - mn);
                l += p;
                const float4* vj = (const float4*)(Vs + (c*16 + j)*KSTR);
                #pragma unroll
                for (int d = 0; d < 16; d++) {
                    float4 vv = vj[d];   // warp-broadcast LDS
                    acc[d].x = fmaf(p, vv.x, acc[d].x);
                    acc[d].y = fmaf(p, vv.y, acc[d].y);
                    acc[d].z = fmaf(p, vv.z, acc[d].z);
                    acc[d].w = fmaf(p, vv.w, acc[d].w);
                }
            }
            m = mn;
        }
    }

    float inv = 1.0f / l;   // diagonal key always valid -> l > 0
    float4* op = (float4*)(O + ((size_t)(b*S_ + row))*D_ + h*HD_);
    #pragma unroll
    for (int d = 0; d < 16; d++)
        op[d] = make_float4(acc[d].x*inv, acc[d].y*inv, acc[d].z*inv, acc[d].w*inv);
}

// ---------------------------------------------------------------------------
extern "C" void kernel_launch(void* const* d_in, const int* in_sizes, int n_in,
                              void* d_out, int out_size)
{
    const float* x  = (const float*)d_in[0];
    const float* wq = (const float*)d_in[1];
    const float* wk = (const float*)d_in[2];
    const float* wv = (const float*)d_in[3];
    const float* wo = (const float*)d_in[4];
    const float* bo = (const float*)d_in[5];
    float* out = (float*)d_out;

    float *qp, *kp, *vp, *cp;
    cudaGetSymbolAddress((void**)&qp, g_q);
    cudaGetSymbolAddress((void**)&kp, g_k);
    cudaGetSymbolAddress((void**)&vp, g_v);
    cudaGetSymbolAddress((void**)&cp, g_c);

    dim3 gg(D_/64, M_/128);           // (16, 32)
    gemm_xwT<<<gg, 256>>>(x, wq, nullptr, qp);
    gemm_xwT<<<gg, 256>>>(x, wk, nullptr, kp);
    gemm_xwT<<<gg, 256>>>(x, wv, nullptr, vp);

    dim3 ga(S_/128, H_, B_);          // (16, 16, 2)
    attn_kernel<<<ga, 128>>>(qp, kp, vp, cp);

    gemm_xwT<<<gg, 256>>>(cp, wo, bo, out);
}

// round 2
// speedup vs baseline: 2.1822x; 2.1822x over previous
#include <cuda_runtime.h>

#define B_  2
#define S_  2048
#define D_  1024
#define H_  16
#define HD_ 64
#define M_  (B_*S_)   // 4096 rows

__device__ float g_q[M_*D_];
__device__ float g_k[M_*D_];
__device__ float g_v[M_*D_];
__device__ float g_c[M_*D_];

// ---------------------------------------------------------------------------
// GEMM: Y[m,n] = sum_k X[m,k] * Wt[n,k] (+bias). 128x128 tile, BK=16,
// 256 threads, 8x8 micro-tile, register prefetch of next k-slab.
// ---------------------------------------------------------------------------
#define GSTR 132
__global__ __launch_bounds__(256,2) void gemm128(
    const float* __restrict__ X, const float* __restrict__ Wt,
    const float* __restrict__ bias, float* __restrict__ Y)
{
    const int K = D_, N = D_;
    __shared__ float Xs[16][GSTR];
    __shared__ float Ws[16][GSTR];

    int t  = threadIdx.x;
    int tx = t & 15, ty = t >> 4;
    int n0 = blockIdx.x * 128;
    int m0 = blockIdx.y * 128;

    int lr = t >> 1;             // 0..127: row loaded by this thread
    int lc = (t & 1) * 8;        // 0 or 8: k-offset
    const float* Xp = X  + (size_t)(m0 + lr) * K + lc;
    const float* Wp = Wt + (size_t)(n0 + lr) * K + lc;

    float acc[8][8];
    #pragma unroll
    for (int i = 0; i < 8; i++)
        #pragma unroll
        for (int j = 0; j < 8; j++) acc[i][j] = 0.f;

    float4 x0 = *(const float4*)(Xp);
    float4 x1 = *(const float4*)(Xp + 4);
    float4 w0 = *(const float4*)(Wp);
    float4 w1 = *(const float4*)(Wp + 4);

    for (int k0 = 0; k0 < K; k0 += 16) {
        __syncthreads();
        Xs[lc+0][lr]=x0.x; Xs[lc+1][lr]=x0.y; Xs[lc+2][lr]=x0.z; Xs[lc+3][lr]=x0.w;
        Xs[lc+4][lr]=x1.x; Xs[lc+5][lr]=x1.y; Xs[lc+6][lr]=x1.z; Xs[lc+7][lr]=x1.w;
        Ws[lc+0][lr]=w0.x; Ws[lc+1][lr]=w0.y; Ws[lc+2][lr]=w0.z; Ws[lc+3][lr]=w0.w;
        Ws[lc+4][lr]=w1.x; Ws[lc+5][lr]=w1.y; Ws[lc+6][lr]=w1.z; Ws[lc+7][lr]=w1.w;
        __syncthreads();

        if (k0 + 16 < K) {
            x0 = *(const float4*)(Xp + k0 + 16);
            x1 = *(const float4*)(Xp + k0 + 20);
            w0 = *(const float4*)(Wp + k0 + 16);
            w1 = *(const float4*)(Wp + k0 + 20);
        }

        #pragma unroll
        for (int kk = 0; kk < 16; kk++) {
            float4 a0 = *(const float4*)&Xs[kk][ty*8];
            float4 a1 = *(const float4*)&Xs[kk][ty*8+4];
            float4 b0 = *(const float4*)&Ws[kk][tx*8];
            float4 b1 = *(const float4*)&Ws[kk][tx*8+4];
            float av[8] = {a0.x,a0.y,a0.z,a0.w,a1.x,a1.y,a1.z,a1.w};
            float bv[8] = {b0.x,b0.y,b0.z,b0.w,b1.x,b1.y,b1.z,b1.w};
            #pragma unroll
            for (int i = 0; i < 8; i++)
                #pragma unroll
                for (int j = 0; j < 8; j++)
                    acc[i][j] = fmaf(av[i], bv[j], acc[i][j]);
        }
    }

    float4 bv0 = make_float4(0.f,0.f,0.f,0.f), bv1 = bv0;
    if (bias) {
        bv0 = *(const float4*)(bias + n0 + tx*8);
        bv1 = *(const float4*)(bias + n0 + tx*8 + 4);
    }
    #pragma unroll
    for (int i = 0; i < 8; i++) {
        float* yp = Y + (size_t)(m0 + ty*8 + i) * N + n0 + tx*8;
        float4 o0 = make_float4(acc[i][0]+bv0.x, acc[i][1]+bv0.y, acc[i][2]+bv0.z, acc[i][3]+bv0.w);
        float4 o1 = make_float4(acc[i][4]+bv1.x, acc[i][5]+bv1.y, acc[i][6]+bv1.z, acc[i][7]+bv1.w);
        *(float4*)(yp)     = o0;
        *(float4*)(yp + 4) = o1;
    }
}

// ---------------------------------------------------------------------------
// Flash attention v2: block = 128 q-rows x one (b,h). 256 threads.
// GEMM1: S = Q*K^T (8x4 micro), shfl row-softmax, P -> smem (k-major),
// GEMM2: O += P*V (8x4 micro). K/V next-tile register prefetch.
// ---------------------------------------------------------------------------
#define QSTR  132   // stride of q-major rows (Qs, Ps): 128 q + pad
#define KSTR2 68    // stride of Ks/Vs rows: 64 + pad

__global__ __launch_bounds__(256,1) void attn2(
    const float* __restrict__ Q, const float* __restrict__ Kg,
    const float* __restrict__ Vg, float* __restrict__ O)
{
    extern __shared__ float sm[];
    float* Qs = sm;                    // [64 d][QSTR]  (k-major: Qs[d][q])
    float* Ks = Qs + 64*QSTR;          // [64 d][KSTR2] (Ks[d][key])
    float* Vs = Ks + 64*KSTR2;         // [64 key][KSTR2] (Vs[key][d])
    float* Ps = Vs + 64*KSTR2;         // [64 key][QSTR] (Ps[key][q])

    int t  = threadIdx.x;
    int tx = t & 15, ty = t >> 4;
    int qt = (int)(gridDim.x - 1u - blockIdx.x);   // heavy tiles first
    int h  = blockIdx.y, b = blockIdx.z;
    int qbase = qt * 128;

    // ---- load Q tile (scaled by 1/sqrt(64)) into Qs, transposed ----
    {
        int qr  = t >> 1;            // 0..127
        int dc0 = (t & 1) * 32;      // 0 or 32 (8 float4)
        const float4* qp = (const float4*)(Q + ((size_t)(b*S_ + qbase + qr))*D_ + h*HD_ + dc0);
        #pragma unroll
        for (int i = 0; i < 8; i++) {
            float4 v = qp[i];
            int d = dc0 + i*4;
            Qs[(d+0)*QSTR + qr] = v.x * 0.125f;
            Qs[(d+1)*QSTR + qr] = v.y * 0.125f;
            Qs[(d+2)*QSTR + qr] = v.z * 0.125f;
            Qs[(d+3)*QSTR + qr] = v.w * 0.125f;
        }
    }

    // K/V loader mapping: each thread loads 4 float4 of K + 4 of V
    int kr  = t >> 2;            // 0..63: key row
    int seg = (t & 3) * 16;      // d-offset (4 float4)
    const float* Kbase = Kg + ((size_t)(b*S_))*D_ + h*HD_;
    const float* Vbase = Vg + ((size_t)(b*S_))*D_ + h*HD_;

    float4 pk[4], pv[4];
    {
        const float4* kp = (const float4*)(Kbase + (size_t)kr*D_ + seg);
        const float4* vp = (const float4*)(Vbase + (size_t)kr*D_ + seg);
        #pragma unroll
        for (int i = 0; i < 4; i++) { pk[i] = kp[i]; pv[i] = vp[i]; }
    }

    float acc[8][4];
    #pragma unroll
    for (int i = 0; i < 8; i++)
        #pragma unroll
        for (int j = 0; j < 4; j++) acc[i][j] = 0.f;
    float mrow[8], lrow[8];
    #pragma unroll
    for (int i = 0; i < 8; i++) { mrow[i] = -1e30f; lrow[i] = 0.f; }

    int ntiles = 2*qt + 2;
    for (int kt = 0; kt < ntiles; kt++) {
        __syncthreads();   // prev GEMM2 / Q-load done before overwriting K/V
        // store prefetched K (transposed) and V (natural)
        #pragma unroll
        for (int i = 0; i < 4; i++) {
            int d = seg + i*4;
            Ks[(d+0)*KSTR2 + kr] = pk[i].x;
            Ks[(d+1)*KSTR2 + kr] = pk[i].y;
            Ks[(d+2)*KSTR2 + kr] = pk[i].z;
            Ks[(d+3)*KSTR2 + kr] = pk[i].w;
        }
        #pragma unroll
        for (int i = 0; i < 4; i++)
            *(float4*)&Vs[kr*KSTR2 + seg + i*4] = pv[i];
        __syncthreads();

        if (kt + 1 < ntiles) {   // prefetch next tile under GEMM1
            const float4* kp = (const float4*)(Kbase + (size_t)((kt+1)*64 + kr)*D_ + seg);
            const float4* vp = (const float4*)(Vbase + (size_t)((kt+1)*64 + kr)*D_ + seg);
            #pragma unroll
            for (int i = 0; i < 4; i++) { pk[i] = kp[i]; pv[i] = vp[i]; }
        }

        // ---- GEMM1: s[8][4] = Q(8 rows) . K^T(4 keys) over d=64 ----
        float s[8][4];
        #pragma unroll
        for (int i = 0; i < 8; i++)
            #pragma unroll
            for (int j = 0; j < 4; j++) s[i][j] = 0.f;

        #pragma unroll 16
        for (int d = 0; d < 64; d++) {
            float4 a0 = *(const float4*)&Qs[d*QSTR + ty*8];
            float4 a1 = *(const float4*)&Qs[d*QSTR + ty*8 + 4];
            float4 bb = *(const float4*)&Ks[d*KSTR2 + tx*4];
            float av[8] = {a0.x,a0.y,a0.z,a0.w,a1.x,a1.y,a1.z,a1.w};
            float bv[4] = {bb.x,bb.y,bb.z,bb.w};
            #pragma unroll
            for (int i = 0; i < 8; i++)
                #pragma unroll
                for (int j = 0; j < 4; j++)
                    s[i][j] = fmaf(av[i], bv[j], s[i][j]);
        }

        // ---- causal mask (only last two tiles are partial) ----
        int kb0 = kt * 64;
        if (kt >= 2*qt) {
            #pragma unroll
            for (int i = 0; i < 8; i++) {
                int qrow = qbase + ty*8 + i;
                #pragma unroll
                for (int j = 0; j < 4; j++)
                    if (kb0 + tx*4 + j > qrow) s[i][j] = -1e30f;
            }
        }

        // ---- online softmax (row reductions across the 16 tx lanes) ----
        #pragma unroll
        for (int i = 0; i < 8; i++) {
            float rm = fmaxf(fmaxf(s[i][0], s[i][1]), fmaxf(s[i][2], s[i][3]));
            rm = fmaxf(rm, __shfl_xor_sync(0xffffffffu, rm, 1));
            rm = fmaxf(rm, __shfl_xor_sync(0xffffffffu, rm, 2));
            rm = fmaxf(rm, __shfl_xor_sync(0xffffffffu, rm, 4));
            rm = fmaxf(rm, __shfl_xor_sync(0xffffffffu, rm, 8));
            float mn = fmaxf(mrow[i], rm);
            float r  = __expf(mrow[i] - mn);
            mrow[i] = mn;
            float psum = 0.f;
            #pragma unroll
            for (int j = 0; j < 4; j++) {
                float p = __expf(s[i][j] - mn);
                Ps[(tx*4 + j)*QSTR + ty*8 + i] = p;
                psum += p;
            }
            psum += __shfl_xor_sync(0xffffffffu, psum, 1);
            psum += __shfl_xor_sync(0xffffffffu, psum, 2);
            psum += __shfl_xor_sync(0xffffffffu, psum, 4);
            psum += __shfl_xor_sync(0xffffffffu, psum, 8);
            lrow[i] = lrow[i]*r + psum;
            #pragma unroll
            for (int j = 0; j < 4; j++) acc[i][j] *= r;
        }
        __syncthreads();   // Ps visible to all

        // ---- GEMM2: acc[8 rows][4 od] += P(8 rows) . V over 64 keys ----
        #pragma unroll 16
        for (int kk = 0; kk < 64; kk++) {
            float4 a0 = *(const float4*)&Ps[kk*QSTR + ty*8];
            float4 a1 = *(const float4*)&Ps[kk*QSTR + ty*8 + 4];
            float4 bb = *(const float4*)&Vs[kk*KSTR2 + tx*4];
            float av[8] = {a0.x,a0.y,a0.z,a0.w,a1.x,a1.y,a1.z,a1.w};
            float bv[4] = {bb.x,bb.y,bb.z,bb.w};
            #pragma unroll
            for (int i = 0; i < 8; i++)
                #pragma unroll
                for (int j = 0; j < 4; j++)
                    acc[i][j] = fmaf(av[i], bv[j], acc[i][j]);
        }
    }

    // ---- normalize and write ----
    #pragma unroll
    for (int i = 0; i < 8; i++) {
        float inv = 1.0f / lrow[i];
        float* op = O + ((size_t)(b*S_ + qbase + ty*8 + i))*D_ + h*HD_ + tx*4;
        *(float4*)op = make_float4(acc[i][0]*inv, acc[i][1]*inv, acc[i][2]*inv, acc[i][3]*inv);
    }
}

#define ATTN_SMEM ((64*QSTR*2 + 64*KSTR2*2) * (int)sizeof(float))   // 102400 B

// ---------------------------------------------------------------------------
extern "C" void kernel_launch(void* const* d_in, const int* in_sizes, int n_in,
                              void* d_out, int out_size)
{
    const float* x  = (const float*)d_in[0];
    const float* wq = (const float*)d_in[1];
    const float* wk = (const float*)d_in[2];
    const float* wv = (const float*)d_in[3];
    const float* wo = (const float*)d_in[4];
    const float* bo = (const float*)d_in[5];
    float* out = (float*)d_out;

    float *qp, *kp, *vp, *cp;
    cudaGetSymbolAddress((void**)&qp, g_q);
    cudaGetSymbolAddress((void**)&kp, g_k);
    cudaGetSymbolAddress((void**)&vp, g_v);
    cudaGetSymbolAddress((void**)&cp, g_c);

    cudaFuncSetAttribute(attn2, cudaFuncAttributeMaxDynamicSharedMemorySize, ATTN_SMEM);

    dim3 gg(D_/128, M_/128);          // (8, 32)
    gemm128<<<gg, 256>>>(x, wq, nullptr, qp);
    gemm128<<<gg, 256>>>(x, wk, nullptr, kp);
    gemm128<<<gg, 256>>>(x, wv, nullptr, vp);

    dim3 ga(S_/128, H_, B_);          // (16, 16, 2)
    attn2<<<ga, 256, ATTN_SMEM>>>(qp, kp, vp, cp);

    gemm128<<<gg, 256>>>(cp, wo, bo, out);
}

// round 5
// speedup vs baseline: 3.1527x; 1.4447x over previous
#include <cuda_runtime.h>
#include <cuda_bf16.h>
#include <cstdint>

#define B_  2
#define S_  2048
#define D_  1024
#define H_  16
#define HD_ 64
#define M_  (B_*S_)   // 4096 rows

// fp32 scratch
__device__ float g_q[M_*D_];
__device__ float g_k[M_*D_];
__device__ float g_v[M_*D_];
__device__ float g_c[M_*D_];
// bf16 split scratch
__device__ __nv_bfloat16 g_xh[M_*D_];
__device__ __nv_bfloat16 g_xl[M_*D_];
__device__ __nv_bfloat16 g_wh[4][D_*D_];
__device__ __nv_bfloat16 g_wl[4][D_*D_];

// ---------------------------------------------------------------------------
// base-ISA PTX helpers (compile for compute_103 generic: no tcgen05!)
// ---------------------------------------------------------------------------
__device__ __forceinline__ uint32_t smem_to_u32(const void* p) {
    uint32_t a;
    asm("{ .reg .u64 tmp; cvta.to.shared.u64 tmp, %1; cvt.u32.u64 %0, tmp; }"
        : "=r"(a) : "l"(p));
    return a;
}
#define CP_ASYNC16(dst, src) \
    asm volatile("cp.async.cg.shared.global [%0], [%1], 16;" :: "r"(dst), "l"(src))
#define CP_COMMIT() asm volatile("cp.async.commit_group;" ::: "memory")
#define CP_WAIT1()  asm volatile("cp.async.wait_group 1;" ::: "memory")

__device__ __forceinline__ void ldmx4(uint32_t* r, uint32_t addr) {
    asm volatile("ldmatrix.sync.aligned.m8n8.x4.shared.b16 {%0,%1,%2,%3}, [%4];"
        : "=r"(r[0]), "=r"(r[1]), "=r"(r[2]), "=r"(r[3]) : "r"(addr));
}
__device__ __forceinline__ void mma16816(float* c, const uint32_t* a, const uint32_t* b) {
    asm volatile("mma.sync.aligned.m16n8k16.row.col.f32.bf16.bf16.f32 "
        "{%0,%1,%2,%3}, {%4,%5,%6,%7}, {%8,%9}, {%0,%1,%2,%3};"
        : "+f"(c[0]), "+f"(c[1]), "+f"(c[2]), "+f"(c[3])
        : "r"(a[0]), "r"(a[1]), "r"(a[2]), "r"(a[3]), "r"(b[0]), "r"(b[1]));
}

// ---------------------------------------------------------------------------
// split: v -> (hi, lo) bf16 pair
// ---------------------------------------------------------------------------
__global__ __launch_bounds__(256) void split_bf16(
    const float* __restrict__ src, __nv_bfloat16* __restrict__ hi,
    __nv_bfloat16* __restrict__ lo, int n4)
{
    int i = blockIdx.x * blockDim.x + threadIdx.x;
    if (i >= n4) return;
    float4 v = ((const float4*)src)[i];
    float hx = __bfloat162float(__float2bfloat16_rn(v.x));
    float hy = __bfloat162float(__float2bfloat16_rn(v.y));
    float hz = __bfloat162float(__float2bfloat16_rn(v.z));
    float hw = __bfloat162float(__float2bfloat16_rn(v.w));
    ((__nv_bfloat162*)hi)[i*2]   = __floats2bfloat162_rn(hx, hy);
    ((__nv_bfloat162*)hi)[i*2+1] = __floats2bfloat162_rn(hz, hw);
    ((__nv_bfloat162*)lo)[i*2]   = __floats2bfloat162_rn(v.x - hx, v.y - hy);
    ((__nv_bfloat162*)lo)[i*2+1] = __floats2bfloat162_rn(v.z - hz, v.w - hw);
}

// ---------------------------------------------------------------------------
// HMMA GEMM: Y = Ah*Bh^T + Ah*Bl^T + Al*Bh^T (+bias), fp32 accum.
// A rows = X [M,1024], B rows = W [N,1024], both bf16 row-major.
// CTA tile 128x128, BK=32, 2-stage cp.async pipeline, 8 warps (4x2),
// warp tile 32x64 = 2 m-tiles x 8 n-tiles of m16n8k16.
// ---------------------------------------------------------------------------
#define BK    32
#define ASTR  40                      // smem row stride (bf16 elems): 80B, conflict-free
#define BUFB  (128*ASTR*2)            // 10240 B per operand buffer
#define STAGEB (4*BUFB)               // Ah, Al, Bh, Bl = 40960 B
#define GSMEM (2*STAGEB)              // 81920 B

__device__ __forceinline__ void stage_load(
    uint32_t sbase,
    const __nv_bfloat16* __restrict__ Ah, const __nv_bfloat16* __restrict__ Al,
    const __nv_bfloat16* __restrict__ Bh, const __nv_bfloat16* __restrict__ Bl,
    int m0, int n0, int kc, int tid)
{
    int r  = tid >> 1;                 // 0..127
    int ch = (tid & 1) * 16;           // bf16 col offset 0/16
    uint32_t so = (uint32_t)(r * (ASTR*2) + ch * 2);
    size_t ga = (size_t)(m0 + r) * D_ + kc + ch;
    size_t gb = (size_t)(n0 + r) * D_ + kc + ch;
    CP_ASYNC16(sbase + 0*BUFB + so,      Ah + ga);
    CP_ASYNC16(sbase + 0*BUFB + so + 16, Ah + ga + 8);
    CP_ASYNC16(sbase + 1*BUFB + so,      Al + ga);
    CP_ASYNC16(sbase + 1*BUFB + so + 16, Al + ga + 8);
    CP_ASYNC16(sbase + 2*BUFB + so,      Bh + gb);
    CP_ASYNC16(sbase + 2*BUFB + so + 16, Bh + gb + 8);
    CP_ASYNC16(sbase + 3*BUFB + so,      Bl + gb);
    CP_ASYNC16(sbase + 3*BUFB + so + 16, Bl + gb + 8);
}

__global__ __launch_bounds__(256) void gemm_hmma(
    const __nv_bfloat16* __restrict__ Ah, const __nv_bfloat16* __restrict__ Al,
    const __nv_bfloat16* __restrict__ Bh, const __nv_bfloat16* __restrict__ Bl,
    const float* __restrict__ bias, float* __restrict__ Y)
{
    extern __shared__ char smem[];
    uint32_t sb = smem_to_u32(smem);
    int tid  = threadIdx.x;
    int wid  = tid >> 5, lane = tid & 31;
    int n0   = blockIdx.x * 128;
    int m0   = blockIdx.y * 128;
    int wm   = (wid >> 1) * 32;        // warp m offset within tile (4 rows of warps)
    int wn   = (wid & 1) * 64;         // warp n offset (2 cols of warps)

    // ldmatrix per-lane address components
    int q  = lane >> 3, lr = lane & 7;
    // A (m16k16 via x4): quads {m+lr,k0},{m+8+lr,k0},{m+lr,k8},{m+8+lr,k8}
    uint32_t a_row = (uint32_t)((q & 1) * 8 + lr);
    uint32_t a_kc  = (uint32_t)((q >> 1) * 8);
    // B (two n8k16 tiles via x4): quads {n+lr,k0},{n+lr,k8},{n+8+lr,k0},{n+8+lr,k8}
    uint32_t b_row = (uint32_t)((q >> 1) * 8 + lr);
    uint32_t b_kc  = (uint32_t)((q & 1) * 8);

    float c[2][8][4];
    #pragma unroll
    for (int mt = 0; mt < 2; mt++)
        #pragma unroll
        for (int nt = 0; nt < 8; nt++)
            #pragma unroll
            for (int i = 0; i < 4; i++) c[mt][nt][i] = 0.f;

    // prologue: stages 0 and 1
    stage_load(sb,          Ah, Al, Bh, Bl, m0, n0, 0,  tid); CP_COMMIT();
    stage_load(sb + STAGEB, Ah, Al, Bh, Bl, m0, n0, BK, tid); CP_COMMIT();

    const int NCH = D_ / BK;   // 32
    for (int cc = 0; cc < NCH; cc++) {
        uint32_t stage = sb + (uint32_t)(cc & 1) * STAGEB;
        CP_WAIT1();
        __syncthreads();

        uint32_t sAh = stage + 0*BUFB, sAl = stage + 1*BUFB;
        uint32_t sBh = stage + 2*BUFB, sBl = stage + 3*BUFB;

        #pragma unroll
        for (int ks = 0; ks < 2; ks++) {
            uint32_t koff = (uint32_t)(ks * 16) * 2;   // bytes
            uint32_t ah[2][4], al[2][4], b[8][2];

            // A hi fragments (2 m-tiles)
            #pragma unroll
            for (int mt = 0; mt < 2; mt++) {
                uint32_t addr = sAh + ((uint32_t)(wm + mt*16) + a_row) * (ASTR*2) + koff + a_kc*2;
                ldmx4(ah[mt], addr);
            }
            // A lo fragments
            #pragma unroll
            for (int mt = 0; mt < 2; mt++) {
                uint32_t addr = sAl + ((uint32_t)(wm + mt*16) + a_row) * (ASTR*2) + koff + a_kc*2;
                ldmx4(al[mt], addr);
            }
            // B hi fragments (8 n-tiles, loaded 2 at a time)
            #pragma unroll
            for (int np = 0; np < 4; np++) {
                uint32_t r4[4];
                uint32_t addr = sBh + ((uint32_t)(wn + np*16) + b_row) * (ASTR*2) + koff + b_kc*2;
                ldmx4(r4, addr);
                b[2*np][0] = r4[0]; b[2*np][1] = r4[1];
                b[2*np+1][0] = r4[2]; b[2*np+1][1] = r4[3];
            }
            // hh + lh passes (B hi in regs)
            #pragma unroll
            for (int mt = 0; mt < 2; mt++)
                #pragma unroll
                for (int nt = 0; nt < 8; nt++)
                    mma16816(c[mt][nt], ah[mt], b[nt]);
            #pragma unroll
            for (int mt = 0; mt < 2; mt++)
                #pragma unroll
                for (int nt = 0; nt < 8; nt++)
                    mma16816(c[mt][nt], al[mt], b[nt]);
            // B lo fragments overwrite b
            #pragma unroll
            for (int np = 0; np < 4; np++) {
                uint32_t r4[4];
                uint32_t addr = sBl + ((uint32_t)(wn + np*16) + b_row) * (ASTR*2) + koff + b_kc*2;
                ldmx4(r4, addr);
                b[2*np][0] = r4[0]; b[2*np][1] = r4[1];
                b[2*np+1][0] = r4[2]; b[2*np+1][1] = r4[3];
            }
            // hl pass
            #pragma unroll
            for (int mt = 0; mt < 2; mt++)
                #pragma unroll
                for (int nt = 0; nt < 8; nt++)
                    mma16816(c[mt][nt], ah[mt], b[nt]);
        }

        __syncthreads();
        if (cc + 2 < NCH)
            stage_load(stage, Ah, Al, Bh, Bl, m0, n0, (cc + 2) * BK, tid);
        CP_COMMIT();   // empty group near the tail keeps wait_group accounting right
    }

    // epilogue
    int crow = lane >> 2, ccol = (lane & 3) * 2;
    #pragma unroll
    for (int mt = 0; mt < 2; mt++) {
        #pragma unroll
        for (int nt = 0; nt < 8; nt++) {
            int m = m0 + wm + mt*16 + crow;
            int n = n0 + wn + nt*8 + ccol;
            float b0 = 0.f, b1 = 0.f;
            if (bias) { b0 = bias[n]; b1 = bias[n+1]; }
            float2 o0 = make_float2(c[mt][nt][0] + b0, c[mt][nt][1] + b1);
            float2 o1 = make_float2(c[mt][nt][2] + b0, c[mt][nt][3] + b1);
            *(float2*)(Y + (size_t)m * D_ + n)       = o0;
            *(float2*)(Y + (size_t)(m+8) * D_ + n)   = o1;
        }
    }
}

// ---------------------------------------------------------------------------
// Flash attention (unchanged R1 kernel — 614us known good; next target)
// ---------------------------------------------------------------------------
#define QSTR  132
#define KSTR2 68

__global__ __launch_bounds__(256,1) void attn2(
    const float* __restrict__ Q, const float* __restrict__ Kg,
    const float* __restrict__ Vg, float* __restrict__ O)
{
    extern __shared__ float sm[];
    float* Qs = sm;
    float* Ks = Qs + 64*QSTR;
    float* Vs = Ks + 64*KSTR2;
    float* Ps = Vs + 64*KSTR2;

    int t  = threadIdx.x;
    int tx = t & 15, ty = t >> 4;
    int qt = (int)(gridDim.x - 1u - blockIdx.x);
    int h  = blockIdx.y, b = blockIdx.z;
    int qbase = qt * 128;

    {
        int qr  = t >> 1;
        int dc0 = (t & 1) * 32;
        const float4* qp = (const float4*)(Q + ((size_t)(b*S_ + qbase + qr))*D_ + h*HD_ + dc0);
        #pragma unroll
        for (int i = 0; i < 8; i++) {
            float4 v = qp[i];
            int d = dc0 + i*4;
            Qs[(d+0)*QSTR + qr] = v.x * 0.125f;
            Qs[(d+1)*QSTR + qr] = v.y * 0.125f;
            Qs[(d+2)*QSTR + qr] = v.z * 0.125f;
            Qs[(d+3)*QSTR + qr] = v.w * 0.125f;
        }
    }

    int kr  = t >> 2;
    int seg = (t & 3) * 16;
    const float* Kbase = Kg + ((size_t)(b*S_))*D_ + h*HD_;
    const float* Vbase = Vg + ((size_t)(b*S_))*D_ + h*HD_;

    float4 pk[4], pv[4];
    {
        const float4* kp = (const float4*)(Kbase + (size_t)kr*D_ + seg);
        const float4* vp = (const float4*)(Vbase + (size_t)kr*D_ + seg);
        #pragma unroll
        for (int i = 0; i < 4; i++) { pk[i] = kp[i]; pv[i] = vp[i]; }
    }

    float acc[8][4];
    #pragma unroll
    for (int i = 0; i < 8; i++)
        #pragma unroll
        for (int j = 0; j < 4; j++) acc[i][j] = 0.f;
    float mrow[8], lrow[8];
    #pragma unroll
    for (int i = 0; i < 8; i++) { mrow[i] = -1e30f; lrow[i] = 0.f; }

    int ntiles = 2*qt + 2;
    for (int kt = 0; kt < ntiles; kt++) {
        __syncthreads();
        #pragma unroll
        for (int i = 0; i < 4; i++) {
            int d = seg + i*4;
            Ks[(d+0)*KSTR2 + kr] = pk[i].x;
            Ks[(d+1)*KSTR2 + kr] = pk[i].y;
            Ks[(d+2)*KSTR2 + kr] = pk[i].z;
            Ks[(d+3)*KSTR2 + kr] = pk[i].w;
        }
        #pragma unroll
        for (int i = 0; i < 4; i++)
            *(float4*)&Vs[kr*KSTR2 + seg + i*4] = pv[i];
        __syncthreads();

        if (kt + 1 < ntiles) {
            const float4* kp = (const float4*)(Kbase + (size_t)((kt+1)*64 + kr)*D_ + seg);
            const float4* vp = (const float4*)(Vbase + (size_t)((kt+1)*64 + kr)*D_ + seg);
            #pragma unroll
            for (int i = 0; i < 4; i++) { pk[i] = kp[i]; pv[i] = vp[i]; }
        }

        float s[8][4];
        #pragma unroll
        for (int i = 0; i < 8; i++)
            #pragma unroll
            for (int j = 0; j < 4; j++) s[i][j] = 0.f;

        #pragma unroll 16
        for (int d = 0; d < 64; d++) {
            float4 a0 = *(const float4*)&Qs[d*QSTR + ty*8];
            float4 a1 = *(const float4*)&Qs[d*QSTR + ty*8 + 4];
            float4 bb = *(const float4*)&Ks[d*KSTR2 + tx*4];
            float av[8] = {a0.x,a0.y,a0.z,a0.w,a1.x,a1.y,a1.z,a1.w};
            float bv[4] = {bb.x,bb.y,bb.z,bb.w};
            #pragma unroll
            for (int i = 0; i < 8; i++)
                #pragma unroll
                for (int j = 0; j < 4; j++)
                    s[i][j] = fmaf(av[i], bv[j], s[i][j]);
        }

        int kb0 = kt * 64;
        if (kt >= 2*qt) {
            #pragma unroll
            for (int i = 0; i < 8; i++) {
                int qrow = qbase + ty*8 + i;
                #pragma unroll
                for (int j = 0; j < 4; j++)
                    if (kb0 + tx*4 + j > qrow) s[i][j] = -1e30f;
            }
        }

        #pragma unroll
        for (int i = 0; i < 8; i++) {
            float rm = fmaxf(fmaxf(s[i][0], s[i][1]), fmaxf(s[i][2], s[i][3]));
            rm = fmaxf(rm, __shfl_xor_sync(0xffffffffu, rm, 1));
            rm = fmaxf(rm, __shfl_xor_sync(0xffffffffu, rm, 2));
            rm = fmaxf(rm, __shfl_xor_sync(0xffffffffu, rm, 4));
            rm = fmaxf(rm, __shfl_xor_sync(0xffffffffu, rm, 8));
            float mn = fmaxf(mrow[i], rm);
            float r  = __expf(mrow[i] - mn);
            mrow[i] = mn;
            float psum = 0.f;
            #pragma unroll
            for (int j = 0; j < 4; j++) {
                float p = __expf(s[i][j] - mn);
                Ps[(tx*4 + j)*QSTR + ty*8 + i] = p;
                psum += p;
            }
            psum += __shfl_xor_sync(0xffffffffu, psum, 1);
            psum += __shfl_xor_sync(0xffffffffu, psum, 2);
            psum += __shfl_xor_sync(0xffffffffu, psum, 4);
            psum += __shfl_xor_sync(0xffffffffu, psum, 8);
            lrow[i] = lrow[i]*r + psum;
            #pragma unroll
            for (int j = 0; j < 4; j++) acc[i][j] *= r;
        }
        __syncthreads();

        #pragma unroll 16
        for (int kk = 0; kk < 64; kk++) {
            float4 a0 = *(const float4*)&Ps[kk*QSTR + ty*8];
            float4 a1 = *(const float4*)&Ps[kk*QSTR + ty*8 + 4];
            float4 bb = *(const float4*)&Vs[kk*KSTR2 + tx*4];
            float av[8] = {a0.x,a0.y,a0.z,a0.w,a1.x,a1.y,a1.z,a1.w};
            float bv[4] = {bb.x,bb.y,bb.z,bb.w};
            #pragma unroll
            for (int i = 0; i < 8; i++)
                #pragma unroll
                for (int j = 0; j < 4; j++)
                    acc[i][j] = fmaf(av[i], bv[j], acc[i][j]);
        }
    }

    #pragma unroll
    for (int i = 0; i < 8; i++) {
        float inv = 1.0f / lrow[i];
        float* op = O + ((size_t)(b*S_ + qbase + ty*8 + i))*D_ + h*HD_ + tx*4;
        *(float4*)op = make_float4(acc[i][0]*inv, acc[i][1]*inv, acc[i][2]*inv, acc[i][3]*inv);
    }
}

#define ATTN_SMEM ((64*QSTR*2 + 64*KSTR2*2) * (int)sizeof(float))

// ---------------------------------------------------------------------------
extern "C" void kernel_launch(void* const* d_in, const int* in_sizes, int n_in,
                              void* d_out, int out_size)
{
    const float* x  = (const float*)d_in[0];
    const float* wq = (const float*)d_in[1];
    const float* wk = (const float*)d_in[2];
    const float* wv = (const float*)d_in[3];
    const float* wo = (const float*)d_in[4];
    const float* bo = (const float*)d_in[5];
    float* out = (float*)d_out;

    float *qp, *kp, *vp, *cp;
    cudaGetSymbolAddress((void**)&qp, g_q);
    cudaGetSymbolAddress((void**)&kp, g_k);
    cudaGetSymbolAddress((void**)&vp, g_v);
    cudaGetSymbolAddress((void**)&cp, g_c);
    __nv_bfloat16 *xh, *xl, *wh, *wl;
    cudaGetSymbolAddress((void**)&xh, g_xh);
    cudaGetSymbolAddress((void**)&xl, g_xl);
    cudaGetSymbolAddress((void**)&wh, g_wh);
    cudaGetSymbolAddress((void**)&wl, g_wl);

    cudaFuncSetAttribute(attn2,     cudaFuncAttributeMaxDynamicSharedMemorySize, ATTN_SMEM);
    cudaFuncSetAttribute(gemm_hmma, cudaFuncAttributeMaxDynamicSharedMemorySize, GSMEM);

    const int NW = D_*D_;
    split_bf16<<<(M_*D_/4 + 255)/256, 256>>>(x, xh, xl, M_*D_/4);
    split_bf16<<<(NW/4 + 255)/256, 256>>>(wq, wh + 0*NW, wl + 0*NW, NW/4);
    split_bf16<<<(NW/4 + 255)/256, 256>>>(wk, wh + 1*NW, wl + 1*NW, NW/4);
    split_bf16<<<(NW/4 + 255)/256, 256>>>(wv, wh + 2*NW, wl + 2*NW, NW/4);
    split_bf16<<<(NW/4 + 255)/256, 256>>>(wo, wh + 3*NW, wl + 3*NW, NW/4);

    dim3 gg(D_/128, M_/128);   // (8, 32)
    gemm_hmma<<<gg, 256, GSMEM>>>(xh, xl, wh + 0*NW, wl + 0*NW, nullptr, qp);
    gemm_hmma<<<gg, 256, GSMEM>>>(xh, xl, wh + 1*NW, wl + 1*NW, nullptr, kp);
    gemm_hmma<<<gg, 256, GSMEM>>>(xh, xl, wh + 2*NW, wl + 2*NW, nullptr, vp);

    dim3 ga(S_/128, H_, B_);   // (16, 16, 2)
    attn2<<<ga, 256, ATTN_SMEM>>>(qp, kp, vp, cp);

    split_bf16<<<(M_*D_/4 + 255)/256, 256>>>(cp, xh, xl, M_*D_/4);
    gemm_hmma<<<gg, 256, GSMEM>>>(xh, xl, wh + 3*NW, wl + 3*NW, bo, out);
}

// round 7
// speedup vs baseline: 5.1076x; 1.6201x over previous
#include <cuda_runtime.h>
#include <cuda_bf16.h>
#include <cstdint>

#define B_  2
#define S_  2048
#define D_  1024
#define H_  16
#define HD_ 64
#define M_  (B_*S_)   // 4096 rows

// fp32 scratch
__device__ float g_q[M_*D_];
__device__ float g_k[M_*D_];
__device__ float g_v[M_*D_];
__device__ float g_c[M_*D_];
// bf16 split scratch (projection GEMMs)
__device__ __nv_bfloat16 g_xh[M_*D_];
__device__ __nv_bfloat16 g_xl[M_*D_];
__device__ __nv_bfloat16 g_wh[4][D_*D_];
__device__ __nv_bfloat16 g_wl[4][D_*D_];
// bf16 split scratch (attention, head-major)
__device__ __nv_bfloat16 g_qh2[M_*D_];
__device__ __nv_bfloat16 g_ql2[M_*D_];
__device__ __nv_bfloat16 g_kh2[M_*D_];
__device__ __nv_bfloat16 g_kl2[M_*D_];
__device__ __nv_bfloat16 g_vth[M_*D_];
__device__ __nv_bfloat16 g_vtl[M_*D_];

// ---------------------------------------------------------------------------
// base-ISA PTX helpers (compute_103 generic: no tcgen05 available!)
// ---------------------------------------------------------------------------
__device__ __forceinline__ uint32_t smem_to_u32(const void* p) {
    uint32_t a;
    asm("{ .reg .u64 tmp; cvta.to.shared.u64 tmp, %1; cvt.u32.u64 %0, tmp; }"
        : "=r"(a) : "l"(p));
    return a;
}
#define CP_ASYNC16(dst, src) \
    asm volatile("cp.async.cg.shared.global [%0], [%1], 16;" :: "r"(dst), "l"(src))
#define CP_COMMIT() asm volatile("cp.async.commit_group;" ::: "memory")
#define CP_WAIT0()  asm volatile("cp.async.wait_group 0;" ::: "memory")
#define CP_WAIT1()  asm volatile("cp.async.wait_group 1;" ::: "memory")

__device__ __forceinline__ void ldmx4(uint32_t* r, uint32_t addr) {
    asm volatile("ldmatrix.sync.aligned.m8n8.x4.shared.b16 {%0,%1,%2,%3}, [%4];"
        : "=r"(r[0]), "=r"(r[1]), "=r"(r[2]), "=r"(r[3]) : "r"(addr));
}
__device__ __forceinline__ void mma16816(float* c, const uint32_t* a, const uint32_t* b) {
    asm volatile("mma.sync.aligned.m16n8k16.row.col.f32.bf16.bf16.f32 "
        "{%0,%1,%2,%3}, {%4,%5,%6,%7}, {%8,%9}, {%0,%1,%2,%3};"
        : "+f"(c[0]), "+f"(c[1]), "+f"(c[2]), "+f"(c[3])
        : "r"(a[0]), "r"(a[1]), "r"(a[2]), "r"(a[3]), "r"(b[0]), "r"(b[1]));
}
__device__ __forceinline__ uint32_t pack_bf2(float a, float b) {   // low=a, high=b
    uint32_t r;
    asm("cvt.rn.bf16x2.f32 %0, %1, %2;" : "=r"(r) : "f"(b), "f"(a));
    return r;
}
__device__ __forceinline__ float bf_res(float x) {
    return x - __bfloat162float(__float2bfloat16_rn(x));
}

// ---------------------------------------------------------------------------
// split: v -> (hi, lo) bf16 pair (layout-preserving; for projection GEMMs)
// ---------------------------------------------------------------------------
__global__ __launch_bounds__(256) void split_bf16(
    const float* __restrict__ src, __nv_bfloat16* __restrict__ hi,
    __nv_bfloat16* __restrict__ lo, int n4)
{
    int i = blockIdx.x * blockDim.x + threadIdx.x;
    if (i >= n4) return;
    float4 v = ((const float4*)src)[i];
    float hx = __bfloat162float(__float2bfloat16_rn(v.x));
    float hy = __bfloat162float(__float2bfloat16_rn(v.y));
    float hz = __bfloat162float(__float2bfloat16_rn(v.z));
    float hw = __bfloat162float(__float2bfloat16_rn(v.w));
    ((__nv_bfloat162*)hi)[i*2]   = __floats2bfloat162_rn(hx, hy);
    ((__nv_bfloat162*)hi)[i*2+1] = __floats2bfloat162_rn(hz, hw);
    ((__nv_bfloat162*)lo)[i*2]   = __floats2bfloat162_rn(v.x - hx, v.y - hy);
    ((__nv_bfloat162*)lo)[i*2+1] = __floats2bfloat162_rn(v.z - hz, v.w - hw);
}

// ---------------------------------------------------------------------------
// qk_convert: fp32 [b,s,D] head-interleaved -> bf16 hi/lo head-major [b,h,s,64]
// (with optional scale; used for Q with 1/sqrt(64) and K with 1.0)
// ---------------------------------------------------------------------------
__global__ __launch_bounds__(256) void qk_convert(
    const float* __restrict__ src, __nv_bfloat16* __restrict__ hi,
    __nv_bfloat16* __restrict__ lo, float scale)
{
    int tid = blockIdx.x * blockDim.x + threadIdx.x;   // M_*D_/2 pairs
    if (tid >= M_*D_/2) return;
    int d2 = tid & 31;
    int s  = (tid >> 5) & (S_-1);
    int bh = tid >> 16;              // S_*32 = 65536
    int b  = bh >> 4, h = bh & 15;
    float2 v = *(const float2*)(src + ((size_t)(b*S_+s))*D_ + h*64 + d2*2);
    float x = v.x * scale, y = v.y * scale;
    float hx = __bfloat162float(__float2bfloat16_rn(x));
    float hy = __bfloat162float(__float2bfloat16_rn(y));
    ((uint32_t*)hi)[tid] = pack_bf2(hx, hy);
    ((uint32_t*)lo)[tid] = pack_bf2(x - hx, y - hy);
}

// ---------------------------------------------------------------------------
// v_transpose: fp32 [b,s,D] -> bf16 hi/lo transposed [b,h,64,s]
// ---------------------------------------------------------------------------
__global__ __launch_bounds__(256) void v_transpose(
    const float* __restrict__ src, __nv_bfloat16* __restrict__ hi,
    __nv_bfloat16* __restrict__ lo)
{
    __shared__ float t[128][65];
    int s0 = blockIdx.x * 128, h = blockIdx.y, b = blockIdx.z;
    int tid = threadIdx.x;
    {
        int sl = tid >> 1, ds = (tid & 1) * 32;
        const float* sp = src + ((size_t)(b*S_ + s0 + sl))*D_ + h*64 + ds;
        #pragma unroll
        for (int i = 0; i < 8; i++) {
            float4 v = *(const float4*)(sp + i*4);
            t[sl][ds+i*4+0] = v.x; t[sl][ds+i*4+1] = v.y;
            t[sl][ds+i*4+2] = v.z; t[sl][ds+i*4+3] = v.w;
        }
    }
    __syncthreads();
    int d = tid >> 2, ss = (tid & 3) * 32;
    uint32_t hp[16], lp[16];
    #pragma unroll
    for (int j = 0; j < 16; j++) {
        float x = t[ss+2*j][d], y = t[ss+2*j+1][d];
        float hx = __bfloat162float(__float2bfloat16_rn(x));
        float hy = __bfloat162float(__float2bfloat16_rn(y));
        hp[j] = pack_bf2(hx, hy);
        lp[j] = pack_bf2(x - hx, y - hy);
    }
    size_t ob = ((size_t)((b*H_ + h)*64 + d))*S_ + s0 + ss;
    #pragma unroll
    for (int j = 0; j < 4; j++) {
        ((uint4*)(hi + ob))[j] = make_uint4(hp[4*j], hp[4*j+1], hp[4*j+2], hp[4*j+3]);
        ((uint4*)(lo + ob))[j] = make_uint4(lp[4*j], lp[4*j+1], lp[4*j+2], lp[4*j+3]);
    }
}

// ---------------------------------------------------------------------------
// HMMA GEMM (unchanged from R4 — validated): Y = Ah*Bh^T + Ah*Bl^T + Al*Bh^T
// ---------------------------------------------------------------------------
#define BK    32
#define ASTR  40
#define BUFB  (128*ASTR*2)
#define STAGEB (4*BUFB)
#define GSMEM (2*STAGEB)

__device__ __forceinline__ void stage_load(
    uint32_t sbase,
    const __nv_bfloat16* __restrict__ Ah, const __nv_bfloat16* __restrict__ Al,
    const __nv_bfloat16* __restrict__ Bh, const __nv_bfloat16* __restrict__ Bl,
    int m0, int n0, int kc, int tid)
{
    int r  = tid >> 1;
    int ch = (tid & 1) * 16;
    uint32_t so = (uint32_t)(r * (ASTR*2) + ch * 2);
    size_t ga = (size_t)(m0 + r) * D_ + kc + ch;
    size_t gb = (size_t)(n0 + r) * D_ + kc + ch;
    CP_ASYNC16(sbase + 0*BUFB + so,      Ah + ga);
    CP_ASYNC16(sbase + 0*BUFB + so + 16, Ah + ga + 8);
    CP_ASYNC16(sbase + 1*BUFB + so,      Al + ga);
    CP_ASYNC16(sbase + 1*BUFB + so + 16, Al + ga + 8);
    CP_ASYNC16(sbase + 2*BUFB + so,      Bh + gb);
    CP_ASYNC16(sbase + 2*BUFB + so + 16, Bh + gb + 8);
    CP_ASYNC16(sbase + 3*BUFB + so,      Bl + gb);
    CP_ASYNC16(sbase + 3*BUFB + so + 16, Bl + gb + 8);
}

__global__ __launch_bounds__(256) void gemm_hmma(
    const __nv_bfloat16* __restrict__ Ah, const __nv_bfloat16* __restrict__ Al,
    const __nv_bfloat16* __restrict__ Bh, const __nv_bfloat16* __restrict__ Bl,
    const float* __restrict__ bias, float* __restrict__ Y)
{
    extern __shared__ char smem[];
    uint32_t sb = smem_to_u32(smem);
    int tid  = threadIdx.x;
    int wid  = tid >> 5, lane = tid & 31;
    int n0   = blockIdx.x * 128;
    int m0   = blockIdx.y * 128;
    int wm   = (wid >> 1) * 32;
    int wn   = (wid & 1) * 64;

    int q  = lane >> 3, lr = lane & 7;
    uint32_t a_row = (uint32_t)((q & 1) * 8 + lr);
    uint32_t a_kc  = (uint32_t)((q >> 1) * 8);
    uint32_t b_row = (uint32_t)((q >> 1) * 8 + lr);
    uint32_t b_kc  = (uint32_t)((q & 1) * 8);

    float c[2][8][4];
    #pragma unroll
    for (int mt = 0; mt < 2; mt++)
        #pragma unroll
        for (int nt = 0; nt < 8; nt++)
            #pragma unroll
            for (int i = 0; i < 4; i++) c[mt][nt][i] = 0.f;

    stage_load(sb,          Ah, Al, Bh, Bl, m0, n0, 0,  tid); CP_COMMIT();
    stage_load(sb + STAGEB, Ah, Al, Bh, Bl, m0, n0, BK, tid); CP_COMMIT();

    const int NCH = D_ / BK;
    for (int cc = 0; cc < NCH; cc++) {
        uint32_t stage = sb + (uint32_t)(cc & 1) * STAGEB;
        CP_WAIT1();
        __syncthreads();

        uint32_t sAh = stage + 0*BUFB, sAl = stage + 1*BUFB;
        uint32_t sBh = stage + 2*BUFB, sBl = stage + 3*BUFB;

        #pragma unroll
        for (int ks = 0; ks < 2; ks++) {
            uint32_t koff = (uint32_t)(ks * 16) * 2;
            uint32_t ah[2][4], al[2][4], b[8][2];
            #pragma unroll
            for (int mt = 0; mt < 2; mt++)
                ldmx4(ah[mt], sAh + ((uint32_t)(wm + mt*16) + a_row) * (ASTR*2) + koff + a_kc*2);
            #pragma unroll
            for (int mt = 0; mt < 2; mt++)
                ldmx4(al[mt], sAl + ((uint32_t)(wm + mt*16) + a_row) * (ASTR*2) + koff + a_kc*2);
            #pragma unroll
            for (int np = 0; np < 4; np++) {
                uint32_t r4[4];
                ldmx4(r4, sBh + ((uint32_t)(wn + np*16) + b_row) * (ASTR*2) + koff + b_kc*2);
                b[2*np][0] = r4[0]; b[2*np][1] = r4[1];
                b[2*np+1][0] = r4[2]; b[2*np+1][1] = r4[3];
            }
            #pragma unroll
            for (int mt = 0; mt < 2; mt++)
                #pragma unroll
                for (int nt = 0; nt < 8; nt++)
                    mma16816(c[mt][nt], ah[mt], b[nt]);
            #pragma unroll
            for (int mt = 0; mt < 2; mt++)
                #pragma unroll
                for (int nt = 0; nt < 8; nt++)
                    mma16816(c[mt][nt], al[mt], b[nt]);
            #pragma unroll
            for (int np = 0; np < 4; np++) {
                uint32_t r4[4];
                ldmx4(r4, sBl + ((uint32_t)(wn + np*16) + b_row) * (ASTR*2) + koff + b_kc*2);
                b[2*np][0] = r4[0]; b[2*np][1] = r4[1];
                b[2*np+1][0] = r4[2]; b[2*np+1][1] = r4[3];
            }
            #pragma unroll
            for (int mt = 0; mt < 2; mt++)
                #pragma unroll
                for (int nt = 0; nt < 8; nt++)
                    mma16816(c[mt][nt], ah[mt], b[nt]);
        }

        __syncthreads();
        if (cc + 2 < NCH)
            stage_load(stage, Ah, Al, Bh, Bl, m0, n0, (cc + 2) * BK, tid);
        CP_COMMIT();
    }

    int crow = lane >> 2, ccol = (lane & 3) * 2;
    #pragma unroll
    for (int mt = 0; mt < 2; mt++) {
        #pragma unroll
        for (int nt = 0; nt < 8; nt++) {
            int m = m0 + wm + mt*16 + crow;
            int n = n0 + wn + nt*8 + ccol;
            float b0 = 0.f, b1 = 0.f;
            if (bias) { b0 = bias[n]; b1 = bias[n+1]; }
            *(float2*)(Y + (size_t)m * D_ + n)     = make_float2(c[mt][nt][0]+b0, c[mt][nt][1]+b1);
            *(float2*)(Y + (size_t)(m+8) * D_ + n) = make_float2(c[mt][nt][2]+b0, c[mt][nt][3]+b1);
        }
    }
}

// ---------------------------------------------------------------------------
// HMMA flash attention. CTA = 128 q-rows x one (b,h). 8 warps x 16 q-rows.
// 64-key tiles, double-buffered cp.async. Split-bf16 3-pass on both GEMMs.
// Smem tiles: Kh,Kl [64 key][64 d]; VTh,VTl [64 d][64 key]; stride 72 bf16.
// ---------------------------------------------------------------------------
#define TSTR  72
#define TROWB (TSTR*2)          // 144 B
#define TILEB (64*TROWB)        // 9216 B
#define ABUF  (4*TILEB)         // 36864 B per stage
#define ATT_SMEM (2*ABUF)       // 73728 B
#define QHB   (128*TROWB)       // 18432 B (Q staging inside buf1)

__device__ __forceinline__ void load_kv(
    uint32_t dst,
    const __nv_bfloat16* __restrict__ Kh, const __nv_bfloat16* __restrict__ Kl,
    const __nv_bfloat16* __restrict__ VTh, const __nv_bfloat16* __restrict__ VTl,
    size_t qko, size_t vto, int kt, int tid)
{
    int r = tid >> 2, seg = (tid & 3) * 16;
    uint32_t off = (uint32_t)(r * TROWB + seg * 2);
    const __nv_bfloat16* kh = Kh  + qko + (size_t)(kt*64 + r)*64 + seg;
    const __nv_bfloat16* kl = Kl  + qko + (size_t)(kt*64 + r)*64 + seg;
    const __nv_bfloat16* vh = VTh + vto + (size_t)r*S_ + kt*64 + seg;
    const __nv_bfloat16* vl = VTl + vto + (size_t)r*S_ + kt*64 + seg;
    CP_ASYNC16(dst + 0*TILEB + off,      kh);  CP_ASYNC16(dst + 0*TILEB + off + 16, kh + 8);
    CP_ASYNC16(dst + 1*TILEB + off,      kl);  CP_ASYNC16(dst + 1*TILEB + off + 16, kl + 8);
    CP_ASYNC16(dst + 2*TILEB + off,      vh);  CP_ASYNC16(dst + 2*TILEB + off + 16, vh + 8);
    CP_ASYNC16(dst + 3*TILEB + off,      vl);  CP_ASYNC16(dst + 3*TILEB + off + 16, vl + 8);
}

__global__ __launch_bounds__(256,1) void attn_hmma(
    const __nv_bfloat16* __restrict__ Qh, const __nv_bfloat16* __restrict__ Ql,
    const __nv_bfloat16* __restrict__ Kh, const __nv_bfloat16* __restrict__ Kl,
    const __nv_bfloat16* __restrict__ VTh, const __nv_bfloat16* __restrict__ VTl,
    float* __restrict__ O)
{
    extern __shared__ char smem[];
    uint32_t sb = smem_to_u32(smem);
    int tid = threadIdx.x, wid = tid >> 5, lane = tid & 31;
    int qt = (int)(gridDim.x - 1u - blockIdx.x);    // heavy tiles first
    int h  = blockIdx.y, b = blockIdx.z;
    int bh = b*H_ + h;
    int qbase = qt * 128;
    size_t qko = (size_t)bh * S_ * 64;
    size_t vto = (size_t)bh * 64 * S_;

    int qq = lane >> 3, lr = lane & 7;
    uint32_t a_row = (uint32_t)((qq & 1) * 8 + lr);
    uint32_t a_kc  = (uint32_t)((qq >> 1) * 8);
    uint32_t b_row = (uint32_t)((qq >> 1) * 8 + lr);
    uint32_t b_kc  = (uint32_t)((qq & 1) * 8);

    // stage Q (hi at buf1+0, lo at buf1+QHB)
    {
        int r = tid >> 1, dseg = (tid & 1) * 32;
        const __nv_bfloat16* qh = Qh + qko + (size_t)(qbase + r)*64 + dseg;
        const __nv_bfloat16* ql = Ql + qko + (size_t)(qbase + r)*64 + dseg;
        uint32_t dq = sb + ABUF + (uint32_t)(r * TROWB + dseg * 2);
        #pragma unroll
        for (int i = 0; i < 4; i++) {
            CP_ASYNC16(dq + i*16,       qh + i*8);
            CP_ASYNC16(dq + QHB + i*16, ql + i*8);
        }
        CP_COMMIT();
    }
    load_kv(sb, Kh, Kl, VTh, VTl, qko, vto, 0, tid);
    CP_COMMIT();

    // Q fragments to registers
    uint32_t qfh[4][4], qfl[4][4];
    CP_WAIT1();            // Q group done (tile0 may still be in flight)
    __syncthreads();
    {
        uint32_t qb = sb + ABUF + ((uint32_t)(wid*16) + a_row) * TROWB + a_kc*2;
        #pragma unroll
        for (int kc = 0; kc < 4; kc++) {
            ldmx4(qfh[kc], qb + kc*32);
            ldmx4(qfl[kc], qb + QHB + kc*32);
        }
    }
    __syncthreads();       // all warps done reading buf1 before overwriting
    int ntiles = 2*qt + 2;
    load_kv(sb + ABUF, Kh, Kl, VTh, VTl, qko, vto, 1, tid);
    CP_COMMIT();

    float o[8][4];
    #pragma unroll
    for (int nt = 0; nt < 8; nt++)
        #pragma unroll
        for (int i = 0; i < 4; i++) o[nt][i] = 0.f;
    float m0 = -1e30f, m1 = -1e30f, l0 = 0.f, l1 = 0.f;

    for (int kt = 0; kt < ntiles; kt++) {
        if (kt + 1 < ntiles) CP_WAIT1(); else CP_WAIT0();
        __syncthreads();
        uint32_t stg = sb + (uint32_t)(kt & 1) * ABUF;

        // ---- GEMM1: S = Qs . K^T, 3 passes ----
        float c[8][4];
        #pragma unroll
        for (int nt = 0; nt < 8; nt++)
            #pragma unroll
            for (int i = 0; i < 4; i++) c[nt][i] = 0.f;

        #pragma unroll
        for (int kc = 0; kc < 4; kc++) {
            uint32_t koff = (uint32_t)(kc * 16) * 2;
            uint32_t bfr[8][2];
            #pragma unroll
            for (int np = 0; np < 4; np++) {
                uint32_t r4[4];
                ldmx4(r4, stg + 0*TILEB + ((uint32_t)(np*16) + b_row) * TROWB + koff + b_kc*2);
                bfr[2*np][0] = r4[0]; bfr[2*np][1] = r4[1];
                bfr[2*np+1][0] = r4[2]; bfr[2*np+1][1] = r4[3];
            }
            #pragma unroll
            for (int nt = 0; nt < 8; nt++) mma16816(c[nt], qfh[kc], bfr[nt]);
            #pragma unroll
            for (int nt = 0; nt < 8; nt++) mma16816(c[nt], qfl[kc], bfr[nt]);
            #pragma unroll
            for (int np = 0; np < 4; np++) {
                uint32_t r4[4];
                ldmx4(r4, stg + 1*TILEB + ((uint32_t)(np*16) + b_row) * TROWB + koff + b_kc*2);
                bfr[2*np][0] = r4[0]; bfr[2*np][1] = r4[1];
                bfr[2*np+1][0] = r4[2]; bfr[2*np+1][1] = r4[3];
            }
            #pragma unroll
            for (int nt = 0; nt < 8; nt++) mma16816(c[nt], qfh[kc], bfr[nt]);
        }

        // ---- causal mask (only the last two tiles are partial) ----
        if (kt >= 2*qt) {
            int kb0 = kt * 64;
            int row0 = qbase + wid*16 + (lane >> 2);
            #pragma unroll
            for (int nt = 0; nt < 8; nt++) {
                int col = kb0 + nt*8 + (lane & 3)*2;
                if (col     > row0)     c[nt][0] = -1e30f;
                if (col + 1 > row0)     c[nt][1] = -1e30f;
                if (col     > row0 + 8) c[nt][2] = -1e30f;
                if (col + 1 > row0 + 8) c[nt][3] = -1e30f;
            }
        }

        // ---- online softmax (rows r0=lane>>2 and r0+8; cols across 4-lane groups) ----
        float mx0 = -1e30f, mx1 = -1e30f;
        #pragma unroll
        for (int nt = 0; nt < 8; nt++) {
            mx0 = fmaxf(mx0, fmaxf(c[nt][0], c[nt][1]));
            mx1 = fmaxf(mx1, fmaxf(c[nt][2], c[nt][3]));
        }
        mx0 = fmaxf(mx0, __shfl_xor_sync(0xffffffffu, mx0, 1));
        mx0 = fmaxf(mx0, __shfl_xor_sync(0xffffffffu, mx0, 2));
        mx1 = fmaxf(mx1, __shfl_xor_sync(0xffffffffu, mx1, 1));
        mx1 = fmaxf(mx1, __shfl_xor_sync(0xffffffffu, mx1, 2));
        float nm0 = fmaxf(m0, mx0), nm1 = fmaxf(m1, mx1);
        float r0 = __expf(m0 - nm0), r1 = __expf(m1 - nm1);
        m0 = nm0; m1 = nm1;
        float s0 = 0.f, s1 = 0.f;
        #pragma unroll
        for (int nt = 0; nt < 8; nt++) {
            c[nt][0] = __expf(c[nt][0] - nm0);
            c[nt][1] = __expf(c[nt][1] - nm0);
            c[nt][2] = __expf(c[nt][2] - nm1);
            c[nt][3] = __expf(c[nt][3] - nm1);
            s0 += c[nt][0] + c[nt][1];
            s1 += c[nt][2] + c[nt][3];
        }
        s0 += __shfl_xor_sync(0xffffffffu, s0, 1);
        s0 += __shfl_xor_sync(0xffffffffu, s0, 2);
        s1 += __shfl_xor_sync(0xffffffffu, s1, 1);
        s1 += __shfl_xor_sync(0xffffffffu, s1, 2);
        l0 = l0 * r0 + s0;
        l1 = l1 * r1 + s1;
        #pragma unroll
        for (int nt = 0; nt < 8; nt++) {
            o[nt][0] *= r0; o[nt][1] *= r0;
            o[nt][2] *= r1; o[nt][3] *= r1;
        }

        // ---- pack P into A-fragments (hi + residual lo), straight from regs ----
        uint32_t ph[4][4], pl[4][4];
        #pragma unroll
        for (int kc = 0; kc < 4; kc++) {
            float* e0 = c[2*kc];
            float* e1 = c[2*kc+1];
            ph[kc][0] = pack_bf2(e0[0], e0[1]);
            ph[kc][1] = pack_bf2(e0[2], e0[3]);
            ph[kc][2] = pack_bf2(e1[0], e1[1]);
            ph[kc][3] = pack_bf2(e1[2], e1[3]);
            pl[kc][0] = pack_bf2(bf_res(e0[0]), bf_res(e0[1]));
            pl[kc][1] = pack_bf2(bf_res(e0[2]), bf_res(e0[3]));
            pl[kc][2] = pack_bf2(bf_res(e1[0]), bf_res(e1[1]));
            pl[kc][3] = pack_bf2(bf_res(e1[2]), bf_res(e1[3]));
        }

        // ---- GEMM2: O += P . V, 3 passes (B from transposed V tiles) ----
        #pragma unroll
        for (int kc = 0; kc < 4; kc++) {
            uint32_t koff = (uint32_t)(kc * 16) * 2;
            uint32_t bfr[8][2];
            #pragma unroll
            for (int np = 0; np < 4; np++) {
                uint32_t r4[4];
                ldmx4(r4, stg + 2*TILEB + ((uint32_t)(np*16) + b_row) * TROWB + koff + b_kc*2);
                bfr[2*np][0] = r4[0]; bfr[2*np][1] = r4[1];
                bfr[2*np+1][0] = r4[2]; bfr[2*np+1][1] = r4[3];
            }
            #pragma unroll
            for (int nt = 0; nt < 8; nt++) mma16816(o[nt], ph[kc], bfr[nt]);
            #pragma unroll
            for (int nt = 0; nt < 8; nt++) mma16816(o[nt], pl[kc], bfr[nt]);
            #pragma unroll
            for (int np = 0; np < 4; np++) {
                uint32_t r4[4];
                ldmx4(r4, stg + 3*TILEB + ((uint32_t)(np*16) + b_row) * TROWB + koff + b_kc*2);
                bfr[2*np][0] = r4[0]; bfr[2*np][1] = r4[1];
                bfr[2*np+1][0] = r4[2]; bfr[2*np+1][1] = r4[3];
            }
            #pragma unroll
            for (int nt = 0; nt < 8; nt++) mma16816(o[nt], ph[kc], bfr[nt]);
        }

        __syncthreads();
        if (kt + 2 < ntiles) {
            load_kv(stg, Kh, Kl, VTh, VTl, qko, vto, kt + 2, tid);
            CP_COMMIT();
        }
    }

    // ---- epilogue: normalize, write fp32 [b,s,D] head-interleaved ----
    float inv0 = 1.0f / l0, inv1 = 1.0f / l1;
    int row0 = qbase + wid*16 + (lane >> 2);
    float* ob0 = O + ((size_t)(b*S_ + row0))*D_ + h*64 + (lane & 3)*2;
    float* ob1 = ob0 + (size_t)8 * D_;
    #pragma unroll
    for (int nt = 0; nt < 8; nt++) {
        *(float2*)(ob0 + nt*8) = make_float2(o[nt][0]*inv0, o[nt][1]*inv0);
        *(float2*)(ob1 + nt*8) = make_float2(o[nt][2]*inv1, o[nt][3]*inv1);
    }
}

// ---------------------------------------------------------------------------
extern "C" void kernel_launch(void* const* d_in, const int* in_sizes, int n_in,
                              void* d_out, int out_size)
{
    const float* x  = (const float*)d_in[0];
    const float* wq = (const float*)d_in[1];
    const float* wk = (const float*)d_in[2];
    const float* wv = (const float*)d_in[3];
    const float* wo = (const float*)d_in[4];
    const float* bo = (const float*)d_in[5];
    float* out = (float*)d_out;

    float *qp, *kp, *vp, *cp;
    cudaGetSymbolAddress((void**)&qp, g_q);
    cudaGetSymbolAddress((void**)&kp, g_k);
    cudaGetSymbolAddress((void**)&vp, g_v);
    cudaGetSymbolAddress((void**)&cp, g_c);
    __nv_bfloat16 *xh, *xl, *wh, *wl, *qh2, *ql2, *kh2, *kl2, *vth, *vtl;
    cudaGetSymbolAddress((void**)&xh,  g_xh);
    cudaGetSymbolAddress((void**)&xl,  g_xl);
    cudaGetSymbolAddress((void**)&wh,  g_wh);
    cudaGetSymbolAddress((void**)&wl,  g_wl);
    cudaGetSymbolAddress((void**)&qh2, g_qh2);
    cudaGetSymbolAddress((void**)&ql2, g_ql2);
    cudaGetSymbolAddress((void**)&kh2, g_kh2);
    cudaGetSymbolAddress((void**)&kl2, g_kl2);
    cudaGetSymbolAddress((void**)&vth, g_vth);
    cudaGetSymbolAddress((void**)&vtl, g_vtl);

    cudaFuncSetAttribute(gemm_hmma, cudaFuncAttributeMaxDynamicSharedMemorySize, GSMEM);
    cudaFuncSetAttribute(attn_hmma, cudaFuncAttributeMaxDynamicSharedMemorySize, ATT_SMEM);

    const int NW = D_*D_;
    split_bf16<<<(M_*D_/4 + 255)/256, 256>>>(x, xh, xl, M_*D_/4);
    split_bf16<<<(NW/4 + 255)/256, 256>>>(wq, wh + 0*NW, wl + 0*NW, NW/4);
    split_bf16<<<(NW/4 + 255)/256, 256>>>(wk, wh + 1*NW, wl + 1*NW, NW/4);
    split_bf16<<<(NW/4 + 255)/256, 256>>>(wv, wh + 2*NW, wl + 2*NW, NW/4);
    split_bf16<<<(NW/4 + 255)/256, 256>>>(wo, wh + 3*NW, wl + 3*NW, NW/4);

    dim3 gg(D_/128, M_/128);   // (8, 32)
    gemm_hmma<<<gg, 256, GSMEM>>>(xh, xl, wh + 0*NW, wl + 0*NW, nullptr, qp);
    gemm_hmma<<<gg, 256, GSMEM>>>(xh, xl, wh + 1*NW, wl + 1*NW, nullptr, kp);
    gemm_hmma<<<gg, 256, GSMEM>>>(xh, xl, wh + 2*NW, wl + 2*NW, nullptr, vp);

    // head-major bf16 splits for attention
    qk_convert<<<(M_*D_/2 + 255)/256, 256>>>(qp, qh2, ql2, 0.125f);   // 1/sqrt(64)
    qk_convert<<<(M_*D_/2 + 255)/256, 256>>>(kp, kh2, kl2, 1.0f);
    v_transpose<<<dim3(S_/128, H_, B_), 256>>>(vp, vth, vtl);

    dim3 ga(S_/128, H_, B_);   // (16, 16, 2)
    attn_hmma<<<ga, 256, ATT_SMEM>>>(qh2, ql2, kh2, kl2, vth, vtl, cp);

    split_bf16<<<(M_*D_/4 + 255)/256, 256>>>(cp, xh, xl, M_*D_/4);
    gemm_hmma<<<gg, 256, GSMEM>>>(xh, xl, wh + 3*NW, wl + 3*NW, bo, out);
}

// round 8
// speedup vs baseline: 5.2381x; 1.0255x over previous
#include <cuda_runtime.h>
#include <cuda_bf16.h>
#include <cstdint>

#define B_  2
#define S_  2048
#define D_  1024
#define H_  16
#define HD_ 64
#define M_  (B_*S_)   // 4096 rows

// fp32 scratch (V only; Q/K/ctx now live as bf16 splits)
__device__ float g_v[M_*D_];
// bf16 split scratch
__device__ __nv_bfloat16 g_xh[M_*D_];
__device__ __nv_bfloat16 g_xl[M_*D_];
__device__ __nv_bfloat16 g_wh[4][D_*D_];
__device__ __nv_bfloat16 g_wl[4][D_*D_];
// attention operands (head-major)
__device__ __nv_bfloat16 g_qh2[M_*D_];
__device__ __nv_bfloat16 g_ql2[M_*D_];
__device__ __nv_bfloat16 g_kh2[M_*D_];
__device__ __nv_bfloat16 g_kl2[M_*D_];
__device__ __nv_bfloat16 g_vth[M_*D_];
__device__ __nv_bfloat16 g_vtl[M_*D_];

// ---------------------------------------------------------------------------
// base-ISA PTX helpers (compute_103 generic: no tcgen05 available)
// ---------------------------------------------------------------------------
__device__ __forceinline__ uint32_t smem_to_u32(const void* p) {
    uint32_t a;
    asm("{ .reg .u64 tmp; cvta.to.shared.u64 tmp, %1; cvt.u32.u64 %0, tmp; }"
        : "=r"(a) : "l"(p));
    return a;
}
#define CP_ASYNC16(dst, src) \
    asm volatile("cp.async.cg.shared.global [%0], [%1], 16;" :: "r"(dst), "l"(src))
#define CP_COMMIT() asm volatile("cp.async.commit_group;" ::: "memory")
#define CP_WAIT0()  asm volatile("cp.async.wait_group 0;" ::: "memory")
#define CP_WAIT1()  asm volatile("cp.async.wait_group 1;" ::: "memory")

__device__ __forceinline__ void ldmx4(uint32_t* r, uint32_t addr) {
    asm volatile("ldmatrix.sync.aligned.m8n8.x4.shared.b16 {%0,%1,%2,%3}, [%4];"
        : "=r"(r[0]), "=r"(r[1]), "=r"(r[2]), "=r"(r[3]) : "r"(addr));
}
__device__ __forceinline__ void mma16816(float* c, const uint32_t* a, const uint32_t* b) {
    asm volatile("mma.sync.aligned.m16n8k16.row.col.f32.bf16.bf16.f32 "
        "{%0,%1,%2,%3}, {%4,%5,%6,%7}, {%8,%9}, {%0,%1,%2,%3};"
        : "+f"(c[0]), "+f"(c[1]), "+f"(c[2]), "+f"(c[3])
        : "r"(a[0]), "r"(a[1]), "r"(a[2]), "r"(a[3]), "r"(b[0]), "r"(b[1]));
}
__device__ __forceinline__ uint32_t pack_bf2(float a, float b) {   // low=a, high=b
    uint32_t r;
    asm("cvt.rn.bf16x2.f32 %0, %1, %2;" : "=r"(r) : "f"(b), "f"(a));
    return r;
}
__device__ __forceinline__ float bf_hi(float x) {
    return __bfloat162float(__float2bfloat16_rn(x));
}
__device__ __forceinline__ float bf_res(float x) { return x - bf_hi(x); }

// ---------------------------------------------------------------------------
// split: v -> (hi, lo) bf16 pair (x and weights)
// ---------------------------------------------------------------------------
__global__ __launch_bounds__(256) void split_bf16(
    const float* __restrict__ src, __nv_bfloat16* __restrict__ hi,
    __nv_bfloat16* __restrict__ lo, int n4)
{
    int i = blockIdx.x * blockDim.x + threadIdx.x;
    if (i >= n4) return;
    float4 v = ((const float4*)src)[i];
    float hx = bf_hi(v.x), hy = bf_hi(v.y), hz = bf_hi(v.z), hw = bf_hi(v.w);
    ((uint32_t*)hi)[i*2]   = pack_bf2(hx, hy);
    ((uint32_t*)hi)[i*2+1] = pack_bf2(hz, hw);
    ((uint32_t*)lo)[i*2]   = pack_bf2(v.x - hx, v.y - hy);
    ((uint32_t*)lo)[i*2+1] = pack_bf2(v.z - hz, v.w - hw);
}

// ---------------------------------------------------------------------------
// v_transpose: fp32 [b,s,D] -> bf16 hi/lo transposed [b,h,64,s]
// ---------------------------------------------------------------------------
__global__ __launch_bounds__(256) void v_transpose(
    const float* __restrict__ src, __nv_bfloat16* __restrict__ hi,
    __nv_bfloat16* __restrict__ lo)
{
    __shared__ float t[128][65];
    int s0 = blockIdx.x * 128, h = blockIdx.y, b = blockIdx.z;
    int tid = threadIdx.x;
    {
        int sl = tid >> 1, ds = (tid & 1) * 32;
        const float* sp = src + ((size_t)(b*S_ + s0 + sl))*D_ + h*64 + ds;
        #pragma unroll
        for (int i = 0; i < 8; i++) {
            float4 v = *(const float4*)(sp + i*4);
            t[sl][ds+i*4+0] = v.x; t[sl][ds+i*4+1] = v.y;
            t[sl][ds+i*4+2] = v.z; t[sl][ds+i*4+3] = v.w;
        }
    }
    __syncthreads();
    int d = tid >> 2, ss = (tid & 3) * 32;
    uint32_t hp[16], lp[16];
    #pragma unroll
    for (int j = 0; j < 16; j++) {
        float x = t[ss+2*j][d], y = t[ss+2*j+1][d];
        float hx = bf_hi(x), hy = bf_hi(y);
        hp[j] = pack_bf2(hx, hy);
        lp[j] = pack_bf2(x - hx, y - hy);
    }
    size_t ob = ((size_t)((b*H_ + h)*64 + d))*S_ + s0 + ss;
    #pragma unroll
    for (int j = 0; j < 4; j++) {
        ((uint4*)(hi + ob))[j] = make_uint4(hp[4*j], hp[4*j+1], hp[4*j+2], hp[4*j+3]);
        ((uint4*)(lo + ob))[j] = make_uint4(lp[4*j], lp[4*j+1], lp[4*j+2], lp[4*j+3]);
    }
}

// ---------------------------------------------------------------------------
// HMMA GEMM core (validated): C = Ah*Bh^T + Ah*Bl^T + Al*Bh^T into c[2][8][4]
// ---------------------------------------------------------------------------
#define BK    32
#define ASTR  40
#define BUFB  (128*ASTR*2)
#define STAGEB (4*BUFB)
#define GSMEM (2*STAGEB)

__device__ __forceinline__ void stage_load(
    uint32_t sbase,
    const __nv_bfloat16* __restrict__ Ah, const __nv_bfloat16* __restrict__ Al,
    const __nv_bfloat16* __restrict__ Bh, const __nv_bfloat16* __restrict__ Bl,
    int m0, int n0, int kc, int tid)
{
    int r  = tid >> 1;
    int ch = (tid & 1) * 16;
    uint32_t so = (uint32_t)(r * (ASTR*2) + ch * 2);
    size_t ga = (size_t)(m0 + r) * D_ + kc + ch;
    size_t gb = (size_t)(n0 + r) * D_ + kc + ch;
    CP_ASYNC16(sbase + 0*BUFB + so,      Ah + ga);
    CP_ASYNC16(sbase + 0*BUFB + so + 16, Ah + ga + 8);
    CP_ASYNC16(sbase + 1*BUFB + so,      Al + ga);
    CP_ASYNC16(sbase + 1*BUFB + so + 16, Al + ga + 8);
    CP_ASYNC16(sbase + 2*BUFB + so,      Bh + gb);
    CP_ASYNC16(sbase + 2*BUFB + so + 16, Bh + gb + 8);
    CP_ASYNC16(sbase + 3*BUFB + so,      Bl + gb);
    CP_ASYNC16(sbase + 3*BUFB + so + 16, Bl + gb + 8);
}

// mainloop macro: fills float c[2][8][4]; uses sb, tid, wid, lane, m0, n0
#define GEMM_MAINLOOP(AhP, AlP, BhP, BlP)                                        \
    int wm = (wid >> 1) * 32;                                                    \
    int wn = (wid & 1) * 64;                                                     \
    int qq = lane >> 3, lr = lane & 7;                                           \
    uint32_t a_row = (uint32_t)((qq & 1) * 8 + lr);                              \
    uint32_t a_kc  = (uint32_t)((qq >> 1) * 8);                                  \
    uint32_t b_row = (uint32_t)((qq >> 1) * 8 + lr);                             \
    uint32_t b_kc  = (uint32_t)((qq & 1) * 8);                                   \
    float c[2][8][4];                                                            \
    _Pragma("unroll")                                                            \
    for (int mt = 0; mt < 2; mt++)                                               \
        _Pragma("unroll")                                                        \
        for (int nt = 0; nt < 8; nt++)                                           \
            _Pragma("unroll")                                                    \
            for (int i = 0; i < 4; i++) c[mt][nt][i] = 0.f;                      \
    stage_load(sb,          AhP, AlP, BhP, BlP, m0, n0, 0,  tid); CP_COMMIT();   \
    stage_load(sb + STAGEB, AhP, AlP, BhP, BlP, m0, n0, BK, tid); CP_COMMIT();   \
    const int NCH = D_ / BK;                                                     \
    for (int cc = 0; cc < NCH; cc++) {                                           \
        uint32_t stage = sb + (uint32_t)(cc & 1) * STAGEB;                       \
        CP_WAIT1();                                                              \
        __syncthreads();                                                         \
        uint32_t sAh = stage + 0*BUFB, sAl = stage + 1*BUFB;                     \
        uint32_t sBh = stage + 2*BUFB, sBl = stage + 3*BUFB;                     \
        _Pragma("unroll")                                                        \
        for (int ks = 0; ks < 2; ks++) {                                         \
            uint32_t koff = (uint32_t)(ks * 16) * 2;                             \
            uint32_t ah[2][4], al[2][4], bfr[8][2];                              \
            _Pragma("unroll")                                                    \
            for (int mt = 0; mt < 2; mt++)                                       \
                ldmx4(ah[mt], sAh + ((uint32_t)(wm + mt*16) + a_row) * (ASTR*2) + koff + a_kc*2); \
            _Pragma("unroll")                                                    \
            for (int mt = 0; mt < 2; mt++)                                       \
                ldmx4(al[mt], sAl + ((uint32_t)(wm + mt*16) + a_row) * (ASTR*2) + koff + a_kc*2); \
            _Pragma("unroll")                                                    \
            for (int np = 0; np < 4; np++) {                                     \
                uint32_t r4[4];                                                  \
                ldmx4(r4, sBh + ((uint32_t)(wn + np*16) + b_row) * (ASTR*2) + koff + b_kc*2); \
                bfr[2*np][0] = r4[0]; bfr[2*np][1] = r4[1];                      \
                bfr[2*np+1][0] = r4[2]; bfr[2*np+1][1] = r4[3];                  \
            }                                                                    \
            _Pragma("unroll")                                                    \
            for (int mt = 0; mt < 2; mt++)                                       \
                _Pragma("unroll")                                                \
                for (int nt = 0; nt < 8; nt++)                                   \
                    mma16816(c[mt][nt], ah[mt], bfr[nt]);                        \
            _Pragma("unroll")                                                    \
            for (int mt = 0; mt < 2; mt++)                                       \
                _Pragma("unroll")                                                \
                for (int nt = 0; nt < 8; nt++)                                   \
                    mma16816(c[mt][nt], al[mt], bfr[nt]);                        \
            _Pragma("unroll")                                                    \
            for (int np = 0; np < 4; np++) {                                     \
                uint32_t r4[4];                                                  \
                ldmx4(r4, sBl + ((uint32_t)(wn + np*16) + b_row) * (ASTR*2) + koff + b_kc*2); \
                bfr[2*np][0] = r4[0]; bfr[2*np][1] = r4[1];                      \
                bfr[2*np+1][0] = r4[2]; bfr[2*np+1][1] = r4[3];                  \
            }                                                                    \
            _Pragma("unroll")                                                    \
            for (int mt = 0; mt < 2; mt++)                                       \
                _Pragma("unroll")                                                \
                for (int nt = 0; nt < 8; nt++)                                   \
                    mma16816(c[mt][nt], ah[mt], bfr[nt]);                        \
        }                                                                        \
        __syncthreads();                                                         \
        if (cc + 2 < NCH)                                                        \
            stage_load(stage, AhP, AlP, BhP, BlP, m0, n0, (cc + 2) * BK, tid);   \
        CP_COMMIT();                                                             \
    }

// ---------------------------------------------------------------------------
// fused QKV projection: z=0 -> Q split head-major (scale 1/8),
//                       z=1 -> K split head-major, z=2 -> V fp32 [b,s,D]
// ---------------------------------------------------------------------------
__global__ __launch_bounds__(256) void gemm_qkv(
    const __nv_bfloat16* __restrict__ Xh, const __nv_bfloat16* __restrict__ Xl,
    const __nv_bfloat16* __restrict__ Wh, const __nv_bfloat16* __restrict__ Wl,
    __nv_bfloat16* __restrict__ Qh, __nv_bfloat16* __restrict__ Ql,
    __nv_bfloat16* __restrict__ Kh, __nv_bfloat16* __restrict__ Kl,
    float* __restrict__ Vf)
{
    extern __shared__ char smem[];
    uint32_t sb = smem_to_u32(smem);
    int tid = threadIdx.x, wid = tid >> 5, lane = tid & 31;
    int n0 = blockIdx.x * 128;
    int m0 = blockIdx.y * 128;
    int z  = blockIdx.z;
    const __nv_bfloat16* Bh = Wh + (size_t)z * D_ * D_;
    const __nv_bfloat16* Bl = Wl + (size_t)z * D_ * D_;

    GEMM_MAINLOOP(Xh, Xl, Bh, Bl)

    int crow = lane >> 2, ccol = (lane & 3) * 2;
    if (z == 2) {
        #pragma unroll
        for (int mt = 0; mt < 2; mt++)
            #pragma unroll
            for (int nt = 0; nt < 8; nt++) {
                int m = m0 + wm + mt*16 + crow;
                int n = n0 + wn + nt*8 + ccol;
                *(float2*)(Vf + (size_t)m * D_ + n)     = make_float2(c[mt][nt][0], c[mt][nt][1]);
                *(float2*)(Vf + (size_t)(m+8) * D_ + n) = make_float2(c[mt][nt][2], c[mt][nt][3]);
            }
    } else {
        float scale = (z == 0) ? 0.125f : 1.0f;
        uint32_t* Yh = (uint32_t*)((z == 0) ? Qh : Kh);
        uint32_t* Yl = (uint32_t*)((z == 0) ? Ql : Kl);
        #pragma unroll
        for (int mt = 0; mt < 2; mt++)
            #pragma unroll
            for (int nt = 0; nt < 8; nt++) {
                int m = m0 + wm + mt*16 + crow;
                int n = n0 + wn + nt*8 + ccol;
                int b = m >> 11, s = m & (S_-1);
                int h = n >> 6,  d = n & 63;
                size_t i0 = (((size_t)(b*H_ + h) * S_ + s) * 64 + d) >> 1;
                size_t i1 = i0 + (8 * 64 >> 1);   // row m+8
                float x0 = c[mt][nt][0]*scale, x1 = c[mt][nt][1]*scale;
                float x2 = c[mt][nt][2]*scale, x3 = c[mt][nt][3]*scale;
                float h0 = bf_hi(x0), h1 = bf_hi(x1), h2 = bf_hi(x2), h3 = bf_hi(x3);
                Yh[i0] = pack_bf2(h0, h1);
                Yl[i0] = pack_bf2(x0 - h0, x1 - h1);
                Yh[i1] = pack_bf2(h2, h3);
                Yl[i1] = pack_bf2(x2 - h2, x3 - h3);
            }
    }
}

// ---------------------------------------------------------------------------
// output projection: A = ctx split, + bias, fp32 out
// ---------------------------------------------------------------------------
__global__ __launch_bounds__(256) void gemm_out(
    const __nv_bfloat16* __restrict__ Ch, const __nv_bfloat16* __restrict__ Cl,
    const __nv_bfloat16* __restrict__ Bh, const __nv_bfloat16* __restrict__ Bl,
    const float* __restrict__ bias, float* __restrict__ Y)
{
    extern __shared__ char smem[];
    uint32_t sb = smem_to_u32(smem);
    int tid = threadIdx.x, wid = tid >> 5, lane = tid & 31;
    int n0 = blockIdx.x * 128;
    int m0 = blockIdx.y * 128;

    GEMM_MAINLOOP(Ch, Cl, Bh, Bl)

    int crow = lane >> 2, ccol = (lane & 3) * 2;
    #pragma unroll
    for (int mt = 0; mt < 2; mt++)
        #pragma unroll
        for (int nt = 0; nt < 8; nt++) {
            int m = m0 + wm + mt*16 + crow;
            int n = n0 + wn + nt*8 + ccol;
            float b0 = bias[n], b1 = bias[n+1];
            *(float2*)(Y + (size_t)m * D_ + n)     = make_float2(c[mt][nt][0]+b0, c[mt][nt][1]+b1);
            *(float2*)(Y + (size_t)(m+8) * D_ + n) = make_float2(c[mt][nt][2]+b0, c[mt][nt][3]+b1);
        }
}

// ---------------------------------------------------------------------------
// HMMA flash attention (validated core). Epilogue now writes split bf16
// layout-preserving [b,s,D] so gemm_out consumes it directly.
// ---------------------------------------------------------------------------
#define TSTR  72
#define TROWB (TSTR*2)
#define TILEB (64*TROWB)
#define ABUF  (4*TILEB)
#define ATT_SMEM (2*ABUF)
#define QHB   (128*TROWB)

__device__ __forceinline__ void load_kv(
    uint32_t dst,
    const __nv_bfloat16* __restrict__ Kh, const __nv_bfloat16* __restrict__ Kl,
    const __nv_bfloat16* __restrict__ VTh, const __nv_bfloat16* __restrict__ VTl,
    size_t qko, size_t vto, int kt, int tid)
{
    int r = tid >> 2, seg = (tid & 3) * 16;
    uint32_t off = (uint32_t)(r * TROWB + seg * 2);
    const __nv_bfloat16* kh = Kh  + qko + (size_t)(kt*64 + r)*64 + seg;
    const __nv_bfloat16* kl = Kl  + qko + (size_t)(kt*64 + r)*64 + seg;
    const __nv_bfloat16* vh = VTh + vto + (size_t)r*S_ + kt*64 + seg;
    const __nv_bfloat16* vl = VTl + vto + (size_t)r*S_ + kt*64 + seg;
    CP_ASYNC16(dst + 0*TILEB + off,      kh);  CP_ASYNC16(dst + 0*TILEB + off + 16, kh + 8);
    CP_ASYNC16(dst + 1*TILEB + off,      kl);  CP_ASYNC16(dst + 1*TILEB + off + 16, kl + 8);
    CP_ASYNC16(dst + 2*TILEB + off,      vh);  CP_ASYNC16(dst + 2*TILEB + off + 16, vh + 8);
    CP_ASYNC16(dst + 3*TILEB + off,      vl);  CP_ASYNC16(dst + 3*TILEB + off + 16, vl + 8);
}

__global__ __launch_bounds__(256,1) void attn_hmma(
    const __nv_bfloat16* __restrict__ Qh, const __nv_bfloat16* __restrict__ Ql,
    const __nv_bfloat16* __restrict__ Kh, const __nv_bfloat16* __restrict__ Kl,
    const __nv_bfloat16* __restrict__ VTh, const __nv_bfloat16* __restrict__ VTl,
    __nv_bfloat16* __restrict__ Oh, __nv_bfloat16* __restrict__ Ol)
{
    extern __shared__ char smem[];
    uint32_t sb = smem_to_u32(smem);
    int tid = threadIdx.x, wid = tid >> 5, lane = tid & 31;
    int qt = (int)(gridDim.x - 1u - blockIdx.x);
    int h  = blockIdx.y, b = blockIdx.z;
    int bh = b*H_ + h;
    int qbase = qt * 128;
    size_t qko = (size_t)bh * S_ * 64;
    size_t vto = (size_t)bh * 64 * S_;

    int qq = lane >> 3, lr = lane & 7;
    uint32_t a_row = (uint32_t)((qq & 1) * 8 + lr);
    uint32_t a_kc  = (uint32_t)((qq >> 1) * 8);
    uint32_t b_row = (uint32_t)((qq >> 1) * 8 + lr);
    uint32_t b_kc  = (uint32_t)((qq & 1) * 8);

    {
        int r = tid >> 1, dseg = (tid & 1) * 32;
        const __nv_bfloat16* qh = Qh + qko + (size_t)(qbase + r)*64 + dseg;
        const __nv_bfloat16* ql = Ql + qko + (size_t)(qbase + r)*64 + dseg;
        uint32_t dq = sb + ABUF + (uint32_t)(r * TROWB + dseg * 2);
        #pragma unroll
        for (int i = 0; i < 4; i++) {
            CP_ASYNC16(dq + i*16,       qh + i*8);
            CP_ASYNC16(dq + QHB + i*16, ql + i*8);
        }
        CP_COMMIT();
    }
    load_kv(sb, Kh, Kl, VTh, VTl, qko, vto, 0, tid);
    CP_COMMIT();

    uint32_t qfh[4][4], qfl[4][4];
    CP_WAIT1();
    __syncthreads();
    {
        uint32_t qb = sb + ABUF + ((uint32_t)(wid*16) + a_row) * TROWB + a_kc*2;
        #pragma unroll
        for (int kc = 0; kc < 4; kc++) {
            ldmx4(qfh[kc], qb + kc*32);
            ldmx4(qfl[kc], qb + QHB + kc*32);
        }
    }
    __syncthreads();
    int ntiles = 2*qt + 2;
    load_kv(sb + ABUF, Kh, Kl, VTh, VTl, qko, vto, 1, tid);
    CP_COMMIT();

    float o[8][4];
    #pragma unroll
    for (int nt = 0; nt < 8; nt++)
        #pragma unroll
        for (int i = 0; i < 4; i++) o[nt][i] = 0.f;
    float m0 = -1e30f, m1 = -1e30f, l0 = 0.f, l1 = 0.f;

    for (int kt = 0; kt < ntiles; kt++) {
        if (kt + 1 < ntiles) CP_WAIT1(); else CP_WAIT0();
        __syncthreads();
        uint32_t stg = sb + (uint32_t)(kt & 1) * ABUF;

        float c[8][4];
        #pragma unroll
        for (int nt = 0; nt < 8; nt++)
            #pragma unroll
            for (int i = 0; i < 4; i++) c[nt][i] = 0.f;

        #pragma unroll
        for (int kc = 0; kc < 4; kc++) {
            uint32_t koff = (uint32_t)(kc * 16) * 2;
            uint32_t bfr[8][2];
            #pragma unroll
            for (int np = 0; np < 4; np++) {
                uint32_t r4[4];
                ldmx4(r4, stg + 0*TILEB + ((uint32_t)(np*16) + b_row) * TROWB + koff + b_kc*2);
                bfr[2*np][0] = r4[0]; bfr[2*np][1] = r4[1];
                bfr[2*np+1][0] = r4[2]; bfr[2*np+1][1] = r4[3];
            }
            #pragma unroll
            for (int nt = 0; nt < 8; nt++) mma16816(c[nt], qfh[kc], bfr[nt]);
            #pragma unroll
            for (int nt = 0; nt < 8; nt++) mma16816(c[nt], qfl[kc], bfr[nt]);
            #pragma unroll
            for (int np = 0; np < 4; np++) {
                uint32_t r4[4];
                ldmx4(r4, stg + 1*TILEB + ((uint32_t)(np*16) + b_row) * TROWB + koff + b_kc*2);
                bfr[2*np][0] = r4[0]; bfr[2*np][1] = r4[1];
                bfr[2*np+1][0] = r4[2]; bfr[2*np+1][1] = r4[3];
            }
            #pragma unroll
            for (int nt = 0; nt < 8; nt++) mma16816(c[nt], qfh[kc], bfr[nt]);
        }

        if (kt >= 2*qt) {
            int kb0 = kt * 64;
            int row0 = qbase + wid*16 + (lane >> 2);
            #pragma unroll
            for (int nt = 0; nt < 8; nt++) {
                int col = kb0 + nt*8 + (lane & 3)*2;
                if (col     > row0)     c[nt][0] = -1e30f;
                if (col + 1 > row0)     c[nt][1] = -1e30f;
                if (col     > row0 + 8) c[nt][2] = -1e30f;
                if (col + 1 > row0 + 8) c[nt][3] = -1e30f;
            }
        }

        float mx0 = -1e30f, mx1 = -1e30f;
        #pragma unroll
        for (int nt = 0; nt < 8; nt++) {
            mx0 = fmaxf(mx0, fmaxf(c[nt][0], c[nt][1]));
            mx1 = fmaxf(mx1, fmaxf(c[nt][2], c[nt][3]));
        }
        mx0 = fmaxf(mx0, __shfl_xor_sync(0xffffffffu, mx0, 1));
        mx0 = fmaxf(mx0, __shfl_xor_sync(0xffffffffu, mx0, 2));
        mx1 = fmaxf(mx1, __shfl_xor_sync(0xffffffffu, mx1, 1));
        mx1 = fmaxf(mx1, __shfl_xor_sync(0xffffffffu, mx1, 2));
        float nm0 = fmaxf(m0, mx0), nm1 = fmaxf(m1, mx1);
        float r0 = __expf(m0 - nm0), r1 = __expf(m1 - nm1);
        m0 = nm0; m1 = nm1;
        float s0 = 0.f, s1 = 0.f;
        #pragma unroll
        for (int nt = 0; nt < 8; nt++) {
            c[nt][0] = __expf(c[nt][0] - nm0);
            c[nt][1] = __expf(c[nt][1] - nm0);
            c[nt][2] = __expf(c[nt][2] - nm1);
            c[nt][3] = __expf(c[nt][3] - nm1);
            s0 += c[nt][0] + c[nt][1];
            s1 += c[nt][2] + c[nt][3];
        }
        s0 += __shfl_xor_sync(0xffffffffu, s0, 1);
        s0 += __shfl_xor_sync(0xffffffffu, s0, 2);
        s1 += __shfl_xor_sync(0xffffffffu, s1, 1);
        s1 += __shfl_xor_sync(0xffffffffu, s1, 2);
        l0 = l0 * r0 + s0;
        l1 = l1 * r1 + s1;
        #pragma unroll
        for (int nt = 0; nt < 8; nt++) {
            o[nt][0] *= r0; o[nt][1] *= r0;
            o[nt][2] *= r1; o[nt][3] *= r1;
        }

        uint32_t ph[4][4], pl[4][4];
        #pragma unroll
        for (int kc = 0; kc < 4; kc++) {
            float* e0 = c[2*kc];
            float* e1 = c[2*kc+1];
            ph[kc][0] = pack_bf2(e0[0], e0[1]);
            ph[kc][1] = pack_bf2(e0[2], e0[3]);
            ph[kc][2] = pack_bf2(e1[0], e1[1]);
            ph[kc][3] = pack_bf2(e1[2], e1[3]);
            pl[kc][0] = pack_bf2(bf_res(e0[0]), bf_res(e0[1]));
            pl[kc][1] = pack_bf2(bf_res(e0[2]), bf_res(e0[3]));
            pl[kc][2] = pack_bf2(bf_res(e1[0]), bf_res(e1[1]));
            pl[kc][3] = pack_bf2(bf_res(e1[2]), bf_res(e1[3]));
        }

        #pragma unroll
        for (int kc = 0; kc < 4; kc++) {
            uint32_t koff = (uint32_t)(kc * 16) * 2;
            uint32_t bfr[8][2];
            #pragma unroll
            for (int np = 0; np < 4; np++) {
                uint32_t r4[4];
                ldmx4(r4, stg + 2*TILEB + ((uint32_t)(np*16) + b_row) * TROWB + koff + b_kc*2);
                bfr[2*np][0] = r4[0]; bfr[2*np][1] = r4[1];
                bfr[2*np+1][0] = r4[2]; bfr[2*np+1][1] = r4[3];
            }
            #pragma unroll
            for (int nt = 0; nt < 8; nt++) mma16816(o[nt], ph[kc], bfr[nt]);
            #pragma unroll
            for (int nt = 0; nt < 8; nt++) mma16816(o[nt], pl[kc], bfr[nt]);
            #pragma unroll
            for (int np = 0; np < 4; np++) {
                uint32_t r4[4];
                ldmx4(r4, stg + 3*TILEB + ((uint32_t)(np*16) + b_row) * TROWB + koff + b_kc*2);
                bfr[2*np][0] = r4[0]; bfr[2*np][1] = r4[1];
                bfr[2*np+1][0] = r4[2]; bfr[2*np+1][1] = r4[3];
            }
            #pragma unroll
            for (int nt = 0; nt < 8; nt++) mma16816(o[nt], ph[kc], bfr[nt]);
        }

        __syncthreads();
        if (kt + 2 < ntiles) {
            load_kv(stg, Kh, Kl, VTh, VTl, qko, vto, kt + 2, tid);
            CP_COMMIT();
        }
    }

    // ---- epilogue: normalize, split to bf16 hi/lo, write [b,s,D] ----
    float inv0 = 1.0f / l0, inv1 = 1.0f / l1;
    int row0 = qbase + wid*16 + (lane >> 2);
    int col0 = h*64 + (lane & 3)*2;
    size_t i0 = (((size_t)(b*S_ + row0))*D_ + col0) >> 1;
    size_t i1 = (((size_t)(b*S_ + row0 + 8))*D_ + col0) >> 1;
    uint32_t* OH = (uint32_t*)Oh;
    uint32_t* OL = (uint32_t*)Ol;
    #pragma unroll
    for (int nt = 0; nt < 8; nt++) {
        float a0 = o[nt][0]*inv0, a1 = o[nt][1]*inv0;
        float a2 = o[nt][2]*inv1, a3 = o[nt][3]*inv1;
        float h0 = bf_hi(a0), h1 = bf_hi(a1), h2 = bf_hi(a2), h3 = bf_hi(a3);
        OH[i0 + nt*4] = pack_bf2(h0, h1);
        OL[i0 + nt*4] = pack_bf2(a0 - h0, a1 - h1);
        OH[i1 + nt*4] = pack_bf2(h2, h3);
        OL[i1 + nt*4] = pack_bf2(a2 - h2, a3 - h3);
    }
}

// ---------------------------------------------------------------------------
extern "C" void kernel_launch(void* const* d_in, const int* in_sizes, int n_in,
                              void* d_out, int out_size)
{
    const float* x  = (const float*)d_in[0];
    const float* wq = (const float*)d_in[1];
    const float* wk = (const float*)d_in[2];
    const float* wv = (const float*)d_in[3];
    const float* wo = (const float*)d_in[4];
    const float* bo = (const float*)d_in[5];
    float* out = (float*)d_out;

    float* vp;
    cudaGetSymbolAddress((void**)&vp, g_v);
    __nv_bfloat16 *xh, *xl, *wh, *wl, *qh2, *ql2, *kh2, *kl2, *vth, *vtl;
    cudaGetSymbolAddress((void**)&xh,  g_xh);
    cudaGetSymbolAddress((void**)&xl,  g_xl);
    cudaGetSymbolAddress((void**)&wh,  g_wh);
    cudaGetSymbolAddress((void**)&wl,  g_wl);
    cudaGetSymbolAddress((void**)&qh2, g_qh2);
    cudaGetSymbolAddress((void**)&ql2, g_ql2);
    cudaGetSymbolAddress((void**)&kh2, g_kh2);
    cudaGetSymbolAddress((void**)&kl2, g_kl2);
    cudaGetSymbolAddress((void**)&vth, g_vth);
    cudaGetSymbolAddress((void**)&vtl, g_vtl);

    cudaFuncSetAttribute(gemm_qkv, cudaFuncAttributeMaxDynamicSharedMemorySize, GSMEM);
    cudaFuncSetAttribute(gemm_out, cudaFuncAttributeMaxDynamicSharedMemorySize, GSMEM);
    cudaFuncSetAttribute(attn_hmma, cudaFuncAttributeMaxDynamicSharedMemorySize, ATT_SMEM);

    const int NW = D_*D_;
    split_bf16<<<(M_*D_/4 + 255)/256, 256>>>(x, xh, xl, M_*D_/4);
    split_bf16<<<(NW/4 + 255)/256, 256>>>(wq, wh + 0*NW, wl + 0*NW, NW/4);
    split_bf16<<<(NW/4 + 255)/256, 256>>>(wk, wh + 1*NW, wl + 1*NW, NW/4);
    split_bf16<<<(NW/4 + 255)/256, 256>>>(wv, wh + 2*NW, wl + 2*NW, NW/4);
    split_bf16<<<(NW/4 + 255)/256, 256>>>(wo, wh + 3*NW, wl + 3*NW, NW/4);

    // fused Q/K/V projection (z selects weight + epilogue)
    dim3 gq(D_/128, M_/128, 3);   // (8, 32, 3)
    gemm_qkv<<<gq, 256, GSMEM>>>(xh, xl, wh, wl, qh2, ql2, kh2, kl2, vp);

    v_transpose<<<dim3(S_/128, H_, B_), 256>>>(vp, vth, vtl);

    dim3 ga(S_/128, H_, B_);   // (16, 16, 2)
    attn_hmma<<<ga, 256, ATT_SMEM>>>(qh2, ql2, kh2, kl2, vth, vtl, xh, xl);

    dim3 gg(D_/128, M_/128);   // (8, 32)
    gemm_out<<<gg, 256, GSMEM>>>(xh, xl, wh + 3*NW, wl + 3*NW, bo, out);
}